// round 12
// baseline (speedup 1.0000x reference)
#include <cuda_runtime.h>
#include <cstdint>
#include <cstddef>

#define HH 384
#define WW 384
#define BB 2
#define NFC 64
#define COUTF 35
#define HWSZ (HH * WW)
#define NIN_EL (BB * 2 * HWSZ)

__device__ float g_bufA[(size_t)BB * NFC * HH * WW];
__device__ float g_bufB[(size_t)BB * NFC * HH * WW];
__device__ float g_core[(size_t)BB * COUTF * HH * WW];
__device__ float g_xin[(size_t)NIN_EL];
__device__ uint2 g_wpack[131328];

__device__ __forceinline__ uint32_t rna_tf32(float f) {
    uint32_t u; asm("cvt.rna.tf32.f32 %0, %1;" : "=r"(u) : "f"(f)); return u;
}
__device__ __forceinline__ uint32_t smem_u32(const void* p) {
    uint32_t a;
    asm("{ .reg .u64 t; cvta.to.shared.u64 t, %1; cvt.u32.u64 %0, t; }" : "=r"(a) : "l"(p));
    return a;
}
__device__ __forceinline__ void cpa4(uint32_t sa, const void* g, int n) {
    asm volatile("cp.async.ca.shared.global [%0], [%1], 4, %2;" :: "r"(sa), "l"(g), "r"(n));
}
__device__ __forceinline__ void cpa16(uint32_t sa, const void* g) {
    asm volatile("cp.async.cg.shared.global [%0], [%1], 16;" :: "r"(sa), "l"(g));
}
#define CPA_COMMIT() asm volatile("cp.async.commit_group;" ::: "memory")
#define CPA_WAIT0()  asm volatile("cp.async.wait_group 0;" ::: "memory")

__device__ __forceinline__ void mma_tf32(float* d, uint32_t a0, uint32_t a1,
                                         uint32_t a2, uint32_t a3,
                                         uint32_t b0, uint32_t b1) {
    asm volatile("mma.sync.aligned.m16n8k8.row.col.f32.tf32.tf32.f32 "
                 "{%0,%1,%2,%3}, {%4,%5,%6,%7}, {%8,%9}, {%0,%1,%2,%3};"
                 : "+f"(d[0]), "+f"(d[1]), "+f"(d[2]), "+f"(d[3])
                 : "r"(a0), "r"(a1), "r"(a2), "r"(a3), "r"(b0), "r"(b1));
}

// ---------------- fused prepass: input rounding + ALL weight packing ----------
__global__ void prepass(const float* __restrict__ xsrc, float* __restrict__ xdst,
                        const float* __restrict__ w0, const float* __restrict__ w1,
                        const float* __restrict__ w2, const float* __restrict__ w3,
                        const float* __restrict__ w4, const float* __restrict__ w5,
                        const float* __restrict__ w6, const float* __restrict__ w7,
                        uint2* __restrict__ wp)
{
    int idx = blockIdx.x * 256 + threadIdx.x;
    if (idx < NIN_EL) {
        xdst[idx] = __uint_as_float(rna_tf32(xsrc[idx]));
        return;
    }
    int wk = idx - NIN_EL;
    if (wk >= 131328) return;
    const float* wgt;
    int CIN, COUT, c, slot;
    if (wk < 2304) {
        wgt = w0; CIN = 2; COUT = NFC; c = 0; slot = wk;
    } else {
        int wk2 = wk - 2304;
        int L = wk2 / 18432;
        int rem = wk2 - L * 18432;
        c = rem / 2304;
        slot = rem - c * 2304;
        CIN = NFC;
        COUT = (L == 7) ? COUTF : NFC;
        const float* tbl[8] = {w0, w1, w2, w3, w4, w5, w6, w7};  // w0 unused here
        wgt = tbl[L + 1 <= 7 ? L + 1 : 7];
        // layers 1..7 map to w1..w7
        wgt = tbl[(L + 1 < 8) ? (L + 1) : 7];
    }
    int tap = slot >> 8, co = (slot >> 2) & 63, q = slot & 3;
    int ci0 = c * 8 + q, ci1 = ci0 + 4;
    uint2 u; u.x = 0; u.y = 0;
    if (co < COUT && ci0 < CIN) u.x = rna_tf32(wgt[((size_t)co * CIN + ci0) * 9 + tap]);
    if (co < COUT && ci1 < CIN) u.y = rna_tf32(wgt[((size_t)co * CIN + ci1) * 9 + tap]);
    wp[wk] = u;
}

// ---------------------------------------------------------------------------
// 3x3 conv as implicit GEMM, tf32 mma.sync, cp.async double-buffered.
// Tile 64 px x 8 rows x 64 co; 512 thr = 16 warps (wm 0..7, wn 0..1),
// warp tile mt=4 x nt=4. X planes: 4 x (10 rows x 68 cols), plane stride 684
// uint2 (684%16==12 -> conflict-free LDS.64 both half-warps).
// smem: X 2x21888B @0, W 2x18432B @43776; total 80640B, 1 block/SM.
// ---------------------------------------------------------------------------
template<int CIN, int COUT, bool RELU, bool RESID, bool ROUND>
__global__ __launch_bounds__(512, 1)
void conv_mma(const float* __restrict__ in, const uint4* __restrict__ wsrc,
              const float* __restrict__ bias, const float* __restrict__ res,
              float* __restrict__ out)
{
    constexpr int CHUNKS = (CIN + 7) / 8;
    extern __shared__ char smem[];
    const uint32_t sbase = smem_u32(smem);

    const int t = threadIdx.x, lane = t & 31, wid = t >> 5;
    const int wm = wid & 7, wn = wid >> 3;
    const int x0 = blockIdx.x * 64, y0 = blockIdx.y * 8, b = blockIdx.z;
    const int gid = lane >> 2, tid4 = lane & 3;

    // ---- X staging slots: 6 per thread (4 planes x 10 rows x 68 cols) ----
    int xsoff[6], xgoff[6];
    uint32_t xfl = 0;
    #pragma unroll
    for (int s6 = 0; s6 < 6; ++s6) {
        xsoff[s6] = -1; xgoff[s6] = 0;
        int ii = t + 512 * s6;
        if (ii < 2720) {
            int pr = ii / 68, s = ii - pr * 68;
            int p = pr & 3, r = pr >> 2;
            int gy = y0 - 1 + r, gx = x0 + s - 1;
            if (s < 66) {
                xsoff[s6] = p * 684 + r * 68 + s;
                bool inb = (gy >= 0 && gy < HH && gx >= 0 && gx < WW);
                if (inb && p < CIN) { xgoff[s6] = p * HWSZ + gy * WW + gx; xfl |= 1u << (2 * s6); }
                if (inb && p + 4 < CIN) xfl |= 2u << (2 * s6);
            }
        }
    }

    float acc[4][4][4];
    #pragma unroll
    for (int mt = 0; mt < 4; ++mt)
        #pragma unroll
        for (int nt = 0; nt < 4; ++nt)
            #pragma unroll
            for (int k = 0; k < 4; ++k) acc[mt][nt][k] = 0.f;

    const int abase = tid4 * 684 + wm * 68 + gid;
    const int bbase = (wn * 32 + gid) * 4 + tid4;
    const float* inb_p = in + (size_t)b * CIN * HWSZ;

    auto prefetch = [&](int c) {
        const uint32_t xb = sbase + (c & 1) * 21888;
        const float* inc = inb_p + (size_t)c * 8 * HWSZ;
        #pragma unroll
        for (int s6 = 0; s6 < 6; ++s6) {
            int so = xsoff[s6];
            if (so >= 0) {
                uint32_t sa = xb + so * 8;
                int f = (int)(xfl >> (2 * s6));
                int n0 = (f & 1) ? 4 : 0;
                int n1 = (f & 2) ? 4 : 0;
                const float* g = inc + xgoff[s6];
                cpa4(sa, g, n0);
                cpa4(sa + 4, n1 ? (g + 4 * HWSZ) : inc, n1);
            }
        }
        const uint32_t wbse = sbase + 43776 + (c & 1) * 18432;
        const uint4* ws = wsrc + (size_t)c * 1152;
        #pragma unroll
        for (int s3 = 0; s3 < 3; ++s3) {
            int i = t + 512 * s3;
            if (i < 1152) cpa16(wbse + i * 16, ws + i);
        }
        CPA_COMMIT();
    };

    prefetch(0);
    for (int c = 0; c < CHUNKS; ++c) {
        CPA_WAIT0();
        __syncthreads();
        if (c + 1 < CHUNKS) prefetch(c + 1);
        const uint2* sX2 = (const uint2*)(smem + (c & 1) * 21888);
        const uint2* sW2 = (const uint2*)(smem + 43776 + (c & 1) * 18432);

        #pragma unroll
        for (int tap = 0; tap < 9; ++tap) {
            const int dy = tap / 3, dx = tap - dy * 3;
            uint2 bf[4];
            #pragma unroll
            for (int nt = 0; nt < 4; ++nt)
                bf[nt] = sW2[tap * 256 + nt * 32 + bbase];
            #pragma unroll
            for (int mt = 0; mt < 4; ++mt) {
                uint2 a02 = sX2[abase + dy * 68 + dx + mt * 16];
                uint2 a13 = sX2[abase + dy * 68 + dx + mt * 16 + 8];
                #pragma unroll
                for (int nt = 0; nt < 4; ++nt)
                    mma_tf32(acc[mt][nt], a02.x, a13.x, a02.y, a13.y,
                             bf[nt].x, bf[nt].y);
            }
        }
    }

    // ---- epilogue ----
    const int y = y0 + wm;
    #pragma unroll
    for (int nt = 0; nt < 4; ++nt) {
        int co0 = wn * 32 + nt * 8 + 2 * tid4;
        int co1 = co0 + 1;
        float bv0 = (co0 < COUT) ? bias[co0] : 0.f;
        float bv1 = (co1 < COUT) ? bias[co1] : 0.f;
        #pragma unroll
        for (int mt = 0; mt < 4; ++mt) {
            int x = x0 + mt * 16 + gid;
            #pragma unroll
            for (int half = 0; half < 2; ++half) {
                int co = half ? co1 : co0;
                float bv = half ? bv1 : bv0;
                if (co < COUT) {
                    size_t o = (((size_t)b * COUT + co) * HH + y) * WW + x;
                    float v = acc[mt][nt][half] + bv;
                    if (RELU) v = fmaxf(v, 0.f);
                    if (RESID) v += res[o];
                    out[o] = ROUND ? __uint_as_float(rna_tf32(v)) : v;
                    float v2 = acc[mt][nt][2 + half] + bv;
                    if (RELU) v2 = fmaxf(v2, 0.f);
                    if (RESID) v2 += res[o + 8];
                    out[o + 8] = ROUND ? __uint_as_float(rna_tf32(v2)) : v2;
                }
            }
        }
    }
}

// ---------------- KPN aggregation (compile-time radial tables) ----------------
#define FST 33
#define FTH 30

struct TEnt { int lo, hi, doff; bool inR; float a, b; };

__host__ __device__ constexpr double csqrt_(double x) {
    double g = x > 1.0 ? x : 1.0;
    for (int i = 0; i < 100; ++i) g = 0.5 * (g + x / g);
    return g;
}
__host__ __device__ constexpr TEnt tentry(int w, int p) {
    const int K = 2 * w - 1, r = w - 1, coff = w * (w - 1) / 2 - 1;
    const int i = p / K, j = p % K;
    TEnt e{};
    e.doff = (i - r) * FST + (j - r);
    const int s2 = (i - r) * (i - r) + (j - r) * (j - r);
    int q = 0;
    while ((q + 1) * (q + 1) <= s2) ++q;
    if (q * q == s2) {
        if (q > r) { e.inR = false; e.lo = coff; e.hi = coff; e.a = 0.f; e.b = 0.f; }
        else       { e.inR = true;  e.lo = coff + q; e.hi = coff + q; e.a = 1.f; e.b = 0.f; }
    } else {
        if (q >= r) { e.inR = false; e.lo = coff; e.hi = coff; e.a = 0.f; e.b = 0.f; }
        else {
            double d = csqrt_((double)s2);
            e.inR = true; e.lo = coff + q; e.hi = coff + q + 1;
            e.a = (float)((double)(q + 1) - d);
            e.b = (float)(d - (double)q);
        }
    }
    return e;
}

template<int W, int Lo, int N>
struct KLoop {
    static __device__ __forceinline__ void run(const float (&c)[COUTF], const float* __restrict__ sF,
                                               int ctr, float& den, float& num) {
        KLoop<W, Lo, N / 2>::run(c, sF, ctr, den, num);
        KLoop<W, Lo + N / 2, N - N / 2>::run(c, sF, ctr, den, num);
    }
};
template<int W, int Lo>
struct KLoop<W, Lo, 1> {
    static __device__ __forceinline__ void run(const float (&c)[COUTF], const float* __restrict__ sF,
                                               int ctr, float& den, float& num) {
        constexpr TEnt e = tentry(W, Lo);
        float patch = sF[ctr + e.doff];
        if constexpr (e.inR) {
            float v = e.a * c[e.lo] + e.b * c[e.hi];
            float tt = __expf(v);
            den += tt; num += tt * patch;
        } else { den += 1.f; num += patch; }
    }
};
template<int W, int Lo>
struct KLoop<W, Lo, 0> {
    static __device__ __forceinline__ void run(const float (&)[COUTF], const float* __restrict__,
                                               int, float&, float&) {}
};

template<int W>
__device__ __forceinline__ float section_run(const float (&c)[COUTF], const float* __restrict__ sF, int ctr) {
    constexpr int K = 2 * W - 1;
    float den = 0.f, num = 0.f;
    KLoop<W, 0, K * K>::run(c, sF, ctr, den, num);
    return num / den;
}

__global__ __launch_bounds__(256)
void kpn_kernel(const float* __restrict__ core, const float* __restrict__ data,
                float* __restrict__ out)
{
    __shared__ float sF[FTH * FST];
    const int t = threadIdx.x, tx = t & 15, ty = t >> 4;
    const int bx = blockIdx.x, by = blockIdx.y, b = blockIdx.z;
    const int x = bx * 16 + tx, y = by * 16 + ty;
    const int oy = by * 16 - 7, ox = bx * 16 - 7;

    for (int idx = t; idx < FTH * FTH; idx += 256) {
        int fy = idx / FTH, fx = idx - fy * FTH;
        int gy = oy + fy, gx = ox + fx;
        float v = 0.f;
        if (gy >= 0 && gy < HH && gx >= 0 && gx < WW)
            v = data[((size_t)b * HH + gy) * WW + gx];
        sF[fy * FST + fx] = v;
    }
    __syncthreads();

    float c[COUTF];
    #pragma unroll
    for (int ch = 0; ch < COUTF; ++ch)
        c[ch] = fabsf(core[(((size_t)b * COUTF + ch) * HH + y) * WW + x]);

    const int ctr = (ty + 7) * FST + (tx + 7);
    float pred = 0.f;
    pred += section_run<2>(c, sF, ctr);
    pred += section_run<3>(c, sF, ctr);
    pred += section_run<4>(c, sF, ctr);
    pred += section_run<5>(c, sF, ctr);
    pred += section_run<6>(c, sF, ctr);
    pred += section_run<7>(c, sF, ctr);
    pred += section_run<8>(c, sF, ctr);

    out[((size_t)b * HH + y) * WW + x] = pred;
}

// ------------------------------- launch --------------------------------------
#define SMEMSZ 80640

extern "C" void kernel_launch(void* const* d_in, const int* in_sizes, int n_in,
                              void* d_out, int out_size) {
    (void)in_sizes; (void)n_in; (void)out_size;
    const float* data_with_est = (const float*)d_in[0];
    const float* data  = (const float*)d_in[1];
    const float* w_first = (const float*)d_in[2];
    const float* b_first = (const float*)d_in[3];
    const float* w1a = (const float*)d_in[4];
    const float* b1a = (const float*)d_in[5];
    const float* w1b = (const float*)d_in[6];
    const float* b1b = (const float*)d_in[7];
    const float* w2a = (const float*)d_in[8];
    const float* b2a = (const float*)d_in[9];
    const float* w2b = (const float*)d_in[10];
    const float* b2b = (const float*)d_in[11];
    const float* w3a = (const float*)d_in[12];
    const float* b3a = (const float*)d_in[13];
    const float* w3b = (const float*)d_in[14];
    const float* b3b = (const float*)d_in[15];
    const float* w_out = (const float*)d_in[16];
    const float* b_out = (const float*)d_in[17];
    float* out = (float*)d_out;

    float *A = nullptr, *Bb = nullptr, *core = nullptr, *xin = nullptr;
    uint2* wp = nullptr;
    cudaGetSymbolAddress((void**)&A, g_bufA);
    cudaGetSymbolAddress((void**)&Bb, g_bufB);
    cudaGetSymbolAddress((void**)&core, g_core);
    cudaGetSymbolAddress((void**)&xin, g_xin);
    cudaGetSymbolAddress((void**)&wp, g_wpack);

    const size_t off0 = 0, off1 = 2304, off2 = 20736, off3 = 39168,
                 off4 = 57600, off5 = 76032, off6 = 94464, off7 = 112896;

    cudaFuncSetAttribute(conv_mma<2, NFC, false, false, true>, cudaFuncAttributeMaxDynamicSharedMemorySize, SMEMSZ);
    cudaFuncSetAttribute(conv_mma<NFC, NFC, true, false, true>, cudaFuncAttributeMaxDynamicSharedMemorySize, SMEMSZ);
    cudaFuncSetAttribute(conv_mma<NFC, NFC, false, true, true>, cudaFuncAttributeMaxDynamicSharedMemorySize, SMEMSZ);
    cudaFuncSetAttribute(conv_mma<NFC, COUTF, false, false, false>, cudaFuncAttributeMaxDynamicSharedMemorySize, SMEMSZ);

    // single fused prepass
    prepass<<<(NIN_EL + 131328 + 255) / 256, 256>>>(
        data_with_est, xin, w_first, w1a, w1b, w2a, w2b, w3a, w3b, w_out, wp);

    dim3 grid(WW / 64, HH / 8, BB), blk(512);

    conv_mma<2, NFC, false, false, true><<<grid, blk, SMEMSZ>>>(xin, (const uint4*)(wp + off0), b_first, nullptr, A);
    conv_mma<NFC, NFC, true,  false, true><<<grid, blk, SMEMSZ>>>(A,  (const uint4*)(wp + off1), b1a, nullptr, Bb);
    conv_mma<NFC, NFC, false, true,  true><<<grid, blk, SMEMSZ>>>(Bb, (const uint4*)(wp + off2), b1b, A, A);
    conv_mma<NFC, NFC, true,  false, true><<<grid, blk, SMEMSZ>>>(A,  (const uint4*)(wp + off3), b2a, nullptr, Bb);
    conv_mma<NFC, NFC, false, true,  true><<<grid, blk, SMEMSZ>>>(Bb, (const uint4*)(wp + off4), b2b, A, A);
    conv_mma<NFC, NFC, true,  false, true><<<grid, blk, SMEMSZ>>>(A,  (const uint4*)(wp + off5), b3a, nullptr, Bb);
    conv_mma<NFC, NFC, false, true,  true><<<grid, blk, SMEMSZ>>>(Bb, (const uint4*)(wp + off6), b3b, A, A);
    conv_mma<NFC, COUTF, false, false, false><<<grid, blk, SMEMSZ>>>(A, (const uint4*)(wp + off7), b_out, nullptr, core);

    kpn_kernel<<<dim3(WW / 16, HH / 16, BB), 256>>>(core, data, out);
}

// round 13
// speedup vs baseline: 1.8797x; 1.8797x over previous
#include <cuda_runtime.h>
#include <cuda_fp16.h>
#include <cstdint>
#include <cstddef>

#define HH 384
#define WW 384
#define BB 2
#define NFC 64
#define COUTF 35
#define HWSZ (HH * WW)
#define NXSLOT (BB * 4 * HWSZ)
#define NWSLOT 66816

__device__ float g_core[(size_t)BB * COUTF * HH * WW];
__device__ uint2 g_hA[(size_t)BB * 16 * HWSZ];
__device__ uint2 g_hB[(size_t)BB * 16 * HWSZ];
__device__ uint2 g_xin[(size_t)BB * 4 * HWSZ];
__device__ uint2 g_wpack[NWSLOT];

__device__ __forceinline__ uint32_t smem_u32(const void* p) {
    uint32_t a;
    asm("{ .reg .u64 t; cvta.to.shared.u64 t, %1; cvt.u32.u64 %0, t; }" : "=r"(a) : "l"(p));
    return a;
}
__device__ __forceinline__ void cpa8(uint32_t sa, const void* g, int n) {
    asm volatile("cp.async.ca.shared.global [%0], [%1], 8, %2;" :: "r"(sa), "l"(g), "r"(n));
}
__device__ __forceinline__ void cpa16(uint32_t sa, const void* g) {
    asm volatile("cp.async.cg.shared.global [%0], [%1], 16;" :: "r"(sa), "l"(g));
}
#define CPA_COMMIT() asm volatile("cp.async.commit_group;" ::: "memory")
#define CPA_WAIT0()  asm volatile("cp.async.wait_group 0;" ::: "memory")

__device__ __forceinline__ void mma_f16(float* d, uint32_t a0, uint32_t a1,
                                        uint32_t a2, uint32_t a3,
                                        uint32_t b0, uint32_t b1) {
    asm volatile("mma.sync.aligned.m16n8k16.row.col.f32.f16.f16.f32 "
                 "{%0,%1,%2,%3}, {%4,%5,%6,%7}, {%8,%9}, {%0,%1,%2,%3};"
                 : "+f"(d[0]), "+f"(d[1]), "+f"(d[2]), "+f"(d[3])
                 : "r"(a0), "r"(a1), "r"(a2), "r"(a3), "r"(b0), "r"(b1));
}
__device__ __forceinline__ uint32_t h2bits(float a, float b) {
    __half2 h = __floats2half2_rn(a, b);
    return *(uint32_t*)&h;
}
__device__ __forceinline__ float2 h2f(uint32_t u) {
    return __half22float2(*(__half2*)&u);
}

// ---------------- fused prepass: pack input + ALL weights to fp16 ------------
__global__ void prepass(const float* __restrict__ xsrc, uint2* __restrict__ xdst,
                        const float* __restrict__ w0, const float* __restrict__ w1,
                        const float* __restrict__ w2, const float* __restrict__ w3,
                        const float* __restrict__ w4, const float* __restrict__ w5,
                        const float* __restrict__ w6, const float* __restrict__ w7,
                        uint2* __restrict__ wp)
{
    int idx = blockIdx.x * 256 + threadIdx.x;
    if (idx < NXSLOT) {
        int b = idx / (4 * HWSZ);
        int rem = idx - b * 4 * HWSZ;
        int q = rem / HWSZ;
        int pix = rem - q * HWSZ;
        uint2 u; u.x = 0; u.y = 0;
        if (q == 0)
            u.x = h2bits(xsrc[(size_t)b * 2 * HWSZ + pix],
                         xsrc[(size_t)(b * 2 + 1) * HWSZ + pix]);
        xdst[idx] = u;
        return;
    }
    int wk = idx - NXSLOT;
    if (wk >= NWSLOT) return;
    const float* tbl[8] = {w0, w1, w2, w3, w4, w5, w6, w7};
    int L, c, slot, CIN, COUT;
    if (wk < 2304) { L = 0; c = 0; slot = wk; CIN = 2; COUT = NFC; }
    else {
        int r = wk - 2304;
        L = 1 + r / 9216;
        int r2 = r - (L - 1) * 9216;
        c = r2 / 2304;
        slot = r2 - c * 2304;
        CIN = NFC;
        COUT = (L == 7) ? COUTF : NFC;
    }
    const float* wgt = tbl[L];
    int tap = slot >> 8, co = (slot >> 2) & 63, q = slot & 3;
    int c0 = c * 16 + 2 * q;
    float f0 = 0.f, f1 = 0.f, f2 = 0.f, f3 = 0.f;
    if (co < COUT) {
        if (c0 < CIN)     f0 = wgt[((size_t)co * CIN + c0) * 9 + tap];
        if (c0 + 1 < CIN) f1 = wgt[((size_t)co * CIN + c0 + 1) * 9 + tap];
        if (c0 + 8 < CIN) f2 = wgt[((size_t)co * CIN + c0 + 8) * 9 + tap];
        if (c0 + 9 < CIN) f3 = wgt[((size_t)co * CIN + c0 + 9) * 9 + tap];
    }
    uint2 u; u.x = h2bits(f0, f1); u.y = h2bits(f2, f3);
    wp[wk] = u;
}

// ---------------------------------------------------------------------------
// 3x3 conv as implicit GEMM, fp16 m16n8k16 mma.sync, cp.async double-buffered.
// Tile 64 px x 8 rows x 64 co; 512 thr = 16 warps (wm 0..7, wn 0..1),
// warp tile mt=4 x nt=4. Activations packed: [b][chunk(16ci)][q 0..3][y][x]
// uint2 = {half2(ci=2q,2q+1), half2(ci=2q+8,2q+9)}.
// X smem: 4 planes x (10 rows x 68), plane stride 684 uint2 (684%16==12 ->
// conflict-free LDS.64). W smem: [tap][co][q] uint2 (as before).
// smem: X 2x21888B @0, W 2x18432B @43776 = 80640B total.
// ---------------------------------------------------------------------------
template<int CIN, int COUT, bool RELU, bool RESID, bool PACKOUT>
__global__ __launch_bounds__(512, 1)
void conv_mma(const uint2* __restrict__ in, const uint4* __restrict__ wsrc,
              const float* __restrict__ bias, const uint2* __restrict__ res,
              void* __restrict__ outv)
{
    constexpr int CHUNKS = (CIN + 15) / 16;
    extern __shared__ char smem[];
    const uint32_t sbase = smem_u32(smem);

    const int t = threadIdx.x, lane = t & 31, wid = t >> 5;
    const int wm = wid & 7, wn = wid >> 3;
    const int x0 = blockIdx.x * 64, y0 = blockIdx.y * 8, b = blockIdx.z;
    const int gid = lane >> 2, tid4 = lane & 3;

    // ---- X staging slots: 6 per thread (4 planes x 10 rows x 68 cols) ----
    int xsoff[6], xgoff[6];
    uint32_t xfl = 0;
    #pragma unroll
    for (int s6 = 0; s6 < 6; ++s6) {
        xsoff[s6] = -1; xgoff[s6] = 0;
        int ii = t + 512 * s6;
        if (ii < 2720) {
            int pr = ii / 68, s = ii - pr * 68;
            int p = pr & 3, r = pr >> 2;
            int gy = y0 - 1 + r, gx = x0 + s - 1;
            if (s < 66) {
                xsoff[s6] = p * 684 + r * 68 + s;
                if (gy >= 0 && gy < HH && gx >= 0 && gx < WW) {
                    xgoff[s6] = p * HWSZ + gy * WW + gx;
                    xfl |= 1u << s6;
                }
            }
        }
    }

    float acc[4][4][4];
    #pragma unroll
    for (int mt = 0; mt < 4; ++mt)
        #pragma unroll
        for (int nt = 0; nt < 4; ++nt)
            #pragma unroll
            for (int k = 0; k < 4; ++k) acc[mt][nt][k] = 0.f;

    const int abase = tid4 * 684 + wm * 68 + gid;
    const int bbase = (wn * 32 + gid) * 4 + tid4;
    const uint2* inb_p = in + (size_t)b * CHUNKS * 4 * HWSZ;

    auto prefetch = [&](int c) {
        const uint32_t xb = sbase + (c & 1) * 21888;
        const uint2* inc = inb_p + (size_t)c * 4 * HWSZ;
        #pragma unroll
        for (int s6 = 0; s6 < 6; ++s6) {
            int so = xsoff[s6];
            if (so >= 0) {
                int n = (xfl >> s6) & 1 ? 8 : 0;
                cpa8(xb + so * 8, inc + xgoff[s6], n);
            }
        }
        const uint32_t wbse = sbase + 43776 + (c & 1) * 18432;
        const uint4* ws = wsrc + (size_t)c * 1152;
        #pragma unroll
        for (int s3 = 0; s3 < 3; ++s3) {
            int i = t + 512 * s3;
            if (i < 1152) cpa16(wbse + i * 16, ws + i);
        }
        CPA_COMMIT();
    };

    prefetch(0);
    for (int c = 0; c < CHUNKS; ++c) {
        CPA_WAIT0();
        __syncthreads();
        if (c + 1 < CHUNKS) prefetch(c + 1);
        const uint2* sX2 = (const uint2*)(smem + (c & 1) * 21888);
        const uint2* sW2 = (const uint2*)(smem + 43776 + (c & 1) * 18432);

        #pragma unroll
        for (int tap = 0; tap < 9; ++tap) {
            const int dy = tap / 3, dx = tap - dy * 3;
            uint2 bf[4];
            #pragma unroll
            for (int nt = 0; nt < 4; ++nt)
                bf[nt] = sW2[tap * 256 + nt * 32 + bbase];
            #pragma unroll
            for (int mt = 0; mt < 4; ++mt) {
                uint2 u = sX2[abase + dy * 68 + dx + mt * 16];
                uint2 v = sX2[abase + dy * 68 + dx + mt * 16 + 8];
                #pragma unroll
                for (int nt = 0; nt < 4; ++nt)
                    mma_f16(acc[mt][nt], u.x, v.x, u.y, v.y, bf[nt].x, bf[nt].y);
            }
        }
    }

    const int y = y0 + wm;
    if constexpr (PACKOUT) {
        uint2* op = (uint2*)outv;
        #pragma unroll
        for (int cq = 0; cq < 2; ++cq) {
            int cb = wn * 32 + 16 * cq + 2 * tid4;
            float bx0 = bias[cb], bx1 = bias[cb + 1];
            float by0 = bias[cb + 8], by1 = bias[cb + 9];
            size_t plane = (((size_t)b * 4 + wn * 2 + cq) * 4 + tid4) * HWSZ + (size_t)y * WW;
            #pragma unroll
            for (int mt = 0; mt < 4; ++mt) {
                #pragma unroll
                for (int h8 = 0; h8 < 2; ++h8) {
                    int x = x0 + mt * 16 + gid + h8 * 8;
                    float vx0 = acc[mt][2 * cq][h8 * 2 + 0] + bx0;
                    float vx1 = acc[mt][2 * cq][h8 * 2 + 1] + bx1;
                    float vy0 = acc[mt][2 * cq + 1][h8 * 2 + 0] + by0;
                    float vy1 = acc[mt][2 * cq + 1][h8 * 2 + 1] + by1;
                    if (RELU) {
                        vx0 = fmaxf(vx0, 0.f); vx1 = fmaxf(vx1, 0.f);
                        vy0 = fmaxf(vy0, 0.f); vy1 = fmaxf(vy1, 0.f);
                    }
                    size_t oi = plane + x;
                    if (RESID) {
                        uint2 r = res[oi];
                        float2 lo = h2f(r.x), hi = h2f(r.y);
                        vx0 += lo.x; vx1 += lo.y; vy0 += hi.x; vy1 += hi.y;
                    }
                    uint2 o; o.x = h2bits(vx0, vx1); o.y = h2bits(vy0, vy1);
                    op[oi] = o;
                }
            }
        }
    } else {
        float* out = (float*)outv;
        #pragma unroll
        for (int nt = 0; nt < 4; ++nt) {
            int co0 = wn * 32 + nt * 8 + 2 * tid4;
            int co1 = co0 + 1;
            float bv0 = (co0 < COUT) ? bias[co0] : 0.f;
            float bv1 = (co1 < COUT) ? bias[co1] : 0.f;
            #pragma unroll
            for (int mt = 0; mt < 4; ++mt) {
                int x = x0 + mt * 16 + gid;
                #pragma unroll
                for (int half = 0; half < 2; ++half) {
                    int co = half ? co1 : co0;
                    float bv = half ? bv1 : bv0;
                    if (co < COUT) {
                        size_t o = (((size_t)b * COUT + co) * HH + y) * WW + x;
                        float v = acc[mt][nt][half] + bv;
                        out[o] = v;
                        float v2 = acc[mt][nt][2 + half] + bv;
                        out[o + 8] = v2;
                    }
                }
            }
        }
    }
}

// ---------------- KPN aggregation (compile-time radial tables) ----------------
#define FST 33
#define FTH 30

struct TEnt { int lo, hi, doff; bool inR; float a, b; };

__host__ __device__ constexpr double csqrt_(double x) {
    double g = x > 1.0 ? x : 1.0;
    for (int i = 0; i < 100; ++i) g = 0.5 * (g + x / g);
    return g;
}
__host__ __device__ constexpr TEnt tentry(int w, int p) {
    const int K = 2 * w - 1, r = w - 1, coff = w * (w - 1) / 2 - 1;
    const int i = p / K, j = p % K;
    TEnt e{};
    e.doff = (i - r) * FST + (j - r);
    const int s2 = (i - r) * (i - r) + (j - r) * (j - r);
    int q = 0;
    while ((q + 1) * (q + 1) <= s2) ++q;
    if (q * q == s2) {
        if (q > r) { e.inR = false; e.lo = coff; e.hi = coff; e.a = 0.f; e.b = 0.f; }
        else       { e.inR = true;  e.lo = coff + q; e.hi = coff + q; e.a = 1.f; e.b = 0.f; }
    } else {
        if (q >= r) { e.inR = false; e.lo = coff; e.hi = coff; e.a = 0.f; e.b = 0.f; }
        else {
            double d = csqrt_((double)s2);
            e.inR = true; e.lo = coff + q; e.hi = coff + q + 1;
            e.a = (float)((double)(q + 1) - d);
            e.b = (float)(d - (double)q);
        }
    }
    return e;
}

template<int W, int Lo, int N>
struct KLoop {
    static __device__ __forceinline__ void run(const float (&c)[COUTF], const float* __restrict__ sF,
                                               int ctr, float& den, float& num) {
        KLoop<W, Lo, N / 2>::run(c, sF, ctr, den, num);
        KLoop<W, Lo + N / 2, N - N / 2>::run(c, sF, ctr, den, num);
    }
};
template<int W, int Lo>
struct KLoop<W, Lo, 1> {
    static __device__ __forceinline__ void run(const float (&c)[COUTF], const float* __restrict__ sF,
                                               int ctr, float& den, float& num) {
        constexpr TEnt e = tentry(W, Lo);
        float patch = sF[ctr + e.doff];
        if constexpr (e.inR) {
            float v = e.a * c[e.lo] + e.b * c[e.hi];
            float tt = __expf(v);
            den += tt; num += tt * patch;
        } else { den += 1.f; num += patch; }
    }
};
template<int W, int Lo>
struct KLoop<W, Lo, 0> {
    static __device__ __forceinline__ void run(const float (&)[COUTF], const float* __restrict__,
                                               int, float&, float&) {}
};

template<int W>
__device__ __forceinline__ float section_run(const float (&c)[COUTF], const float* __restrict__ sF, int ctr) {
    constexpr int K = 2 * W - 1;
    float den = 0.f, num = 0.f;
    KLoop<W, 0, K * K>::run(c, sF, ctr, den, num);
    return num / den;
}

__global__ __launch_bounds__(256)
void kpn_kernel(const float* __restrict__ core, const float* __restrict__ data,
                float* __restrict__ out)
{
    __shared__ float sF[FTH * FST];
    const int t = threadIdx.x, tx = t & 15, ty = t >> 4;
    const int bx = blockIdx.x, by = blockIdx.y, b = blockIdx.z;
    const int x = bx * 16 + tx, y = by * 16 + ty;
    const int oy = by * 16 - 7, ox = bx * 16 - 7;

    for (int idx = t; idx < FTH * FTH; idx += 256) {
        int fy = idx / FTH, fx = idx - fy * FTH;
        int gy = oy + fy, gx = ox + fx;
        float v = 0.f;
        if (gy >= 0 && gy < HH && gx >= 0 && gx < WW)
            v = data[((size_t)b * HH + gy) * WW + gx];
        sF[fy * FST + fx] = v;
    }
    __syncthreads();

    float c[COUTF];
    #pragma unroll
    for (int ch = 0; ch < COUTF; ++ch)
        c[ch] = fabsf(core[(((size_t)b * COUTF + ch) * HH + y) * WW + x]);

    const int ctr = (ty + 7) * FST + (tx + 7);
    float pred = 0.f;
    pred += section_run<2>(c, sF, ctr);
    pred += section_run<3>(c, sF, ctr);
    pred += section_run<4>(c, sF, ctr);
    pred += section_run<5>(c, sF, ctr);
    pred += section_run<6>(c, sF, ctr);
    pred += section_run<7>(c, sF, ctr);
    pred += section_run<8>(c, sF, ctr);

    out[((size_t)b * HH + y) * WW + x] = pred;
}

// ------------------------------- launch --------------------------------------
#define SMEMSZ 80640

extern "C" void kernel_launch(void* const* d_in, const int* in_sizes, int n_in,
                              void* d_out, int out_size) {
    (void)in_sizes; (void)n_in; (void)out_size;
    const float* data_with_est = (const float*)d_in[0];
    const float* data  = (const float*)d_in[1];
    const float* w_first = (const float*)d_in[2];
    const float* b_first = (const float*)d_in[3];
    const float* w1a = (const float*)d_in[4];
    const float* b1a = (const float*)d_in[5];
    const float* w1b = (const float*)d_in[6];
    const float* b1b = (const float*)d_in[7];
    const float* w2a = (const float*)d_in[8];
    const float* b2a = (const float*)d_in[9];
    const float* w2b = (const float*)d_in[10];
    const float* b2b = (const float*)d_in[11];
    const float* w3a = (const float*)d_in[12];
    const float* b3a = (const float*)d_in[13];
    const float* w3b = (const float*)d_in[14];
    const float* b3b = (const float*)d_in[15];
    const float* w_out = (const float*)d_in[16];
    const float* b_out = (const float*)d_in[17];
    float* out = (float*)d_out;

    float *core = nullptr;
    uint2 *hA = nullptr, *hB = nullptr, *xin = nullptr, *wp = nullptr;
    cudaGetSymbolAddress((void**)&core, g_core);
    cudaGetSymbolAddress((void**)&hA, g_hA);
    cudaGetSymbolAddress((void**)&hB, g_hB);
    cudaGetSymbolAddress((void**)&xin, g_xin);
    cudaGetSymbolAddress((void**)&wp, g_wpack);

    const size_t o0 = 0, o1 = 2304, o2 = 11520, o3 = 20736,
                 o4 = 29952, o5 = 39168, o6 = 48384, o7 = 57600;

    cudaFuncSetAttribute(conv_mma<2, NFC, false, false, true>, cudaFuncAttributeMaxDynamicSharedMemorySize, SMEMSZ);
    cudaFuncSetAttribute(conv_mma<NFC, NFC, true, false, true>, cudaFuncAttributeMaxDynamicSharedMemorySize, SMEMSZ);
    cudaFuncSetAttribute(conv_mma<NFC, NFC, false, true, true>, cudaFuncAttributeMaxDynamicSharedMemorySize, SMEMSZ);
    cudaFuncSetAttribute(conv_mma<NFC, COUTF, false, false, false>, cudaFuncAttributeMaxDynamicSharedMemorySize, SMEMSZ);

    prepass<<<(NXSLOT + NWSLOT + 255) / 256, 256>>>(
        data_with_est, xin, w_first, w1a, w1b, w2a, w2b, w3a, w3b, w_out, wp);

    dim3 grid(WW / 64, HH / 8, BB), blk(512);

    conv_mma<2, NFC, false, false, true><<<grid, blk, SMEMSZ>>>(xin, (const uint4*)(wp + o0), b_first, nullptr, hA);
    conv_mma<NFC, NFC, true,  false, true><<<grid, blk, SMEMSZ>>>(hA, (const uint4*)(wp + o1), b1a, nullptr, hB);
    conv_mma<NFC, NFC, false, true,  true><<<grid, blk, SMEMSZ>>>(hB, (const uint4*)(wp + o2), b1b, hA, hA);
    conv_mma<NFC, NFC, true,  false, true><<<grid, blk, SMEMSZ>>>(hA, (const uint4*)(wp + o3), b2a, nullptr, hB);
    conv_mma<NFC, NFC, false, true,  true><<<grid, blk, SMEMSZ>>>(hB, (const uint4*)(wp + o4), b2b, hA, hA);
    conv_mma<NFC, NFC, true,  false, true><<<grid, blk, SMEMSZ>>>(hA, (const uint4*)(wp + o5), b3a, nullptr, hB);
    conv_mma<NFC, NFC, false, true,  true><<<grid, blk, SMEMSZ>>>(hB, (const uint4*)(wp + o6), b3b, hA, hA);
    conv_mma<NFC, COUTF, false, false, false><<<grid, blk, SMEMSZ>>>(hA, (const uint4*)(wp + o7), b_out, nullptr, core);

    kpn_kernel<<<dim3(WW / 16, HH / 16, BB), 256>>>(core, data, out);
}

// round 14
// speedup vs baseline: 1.9472x; 1.0359x over previous
#include <cuda_runtime.h>
#include <cuda_fp16.h>
#include <cstdint>
#include <cstddef>

#define HH 384
#define WW 384
#define BB 2
#define NFC 64
#define COUTF 35
#define HWSZ (HH * WW)
#define NXSLOT (BB * 4 * HWSZ)
#define NWSLOT 63360   // 2304 + 6*9216 + 5760 (fused out-conv, co padded to 40)

__device__ uint2 g_hA[(size_t)BB * 16 * HWSZ];
__device__ uint2 g_hB[(size_t)BB * 16 * HWSZ];
__device__ uint2 g_xin[(size_t)BB * 4 * HWSZ];
__device__ uint2 g_wpack[NWSLOT];

__device__ __forceinline__ uint32_t smem_u32(const void* p) {
    uint32_t a;
    asm("{ .reg .u64 t; cvta.to.shared.u64 t, %1; cvt.u32.u64 %0, t; }" : "=r"(a) : "l"(p));
    return a;
}
__device__ __forceinline__ void cpa8(uint32_t sa, const void* g, int n) {
    asm volatile("cp.async.ca.shared.global [%0], [%1], 8, %2;" :: "r"(sa), "l"(g), "r"(n));
}
__device__ __forceinline__ void cpa16(uint32_t sa, const void* g) {
    asm volatile("cp.async.cg.shared.global [%0], [%1], 16;" :: "r"(sa), "l"(g));
}
#define CPA_COMMIT() asm volatile("cp.async.commit_group;" ::: "memory")
#define CPA_WAIT0()  asm volatile("cp.async.wait_group 0;" ::: "memory")

__device__ __forceinline__ void mma_f16(float* d, uint32_t a0, uint32_t a1,
                                        uint32_t a2, uint32_t a3,
                                        uint32_t b0, uint32_t b1) {
    asm volatile("mma.sync.aligned.m16n8k16.row.col.f32.f16.f16.f32 "
                 "{%0,%1,%2,%3}, {%4,%5,%6,%7}, {%8,%9}, {%0,%1,%2,%3};"
                 : "+f"(d[0]), "+f"(d[1]), "+f"(d[2]), "+f"(d[3])
                 : "r"(a0), "r"(a1), "r"(a2), "r"(a3), "r"(b0), "r"(b1));
}
__device__ __forceinline__ uint32_t h2bits(float a, float b) {
    __half2 h = __floats2half2_rn(a, b);
    return *(uint32_t*)&h;
}
__device__ __forceinline__ float2 h2f(uint32_t u) {
    return __half22float2(*(__half2*)&u);
}

// ---------------- fused prepass: pack input + ALL weights to fp16 ------------
__global__ void prepass(const float* __restrict__ xsrc, uint2* __restrict__ xdst,
                        const float* __restrict__ w0, const float* __restrict__ w1,
                        const float* __restrict__ w2, const float* __restrict__ w3,
                        const float* __restrict__ w4, const float* __restrict__ w5,
                        const float* __restrict__ w6, const float* __restrict__ w7,
                        uint2* __restrict__ wp)
{
    int idx = blockIdx.x * 256 + threadIdx.x;
    if (idx < NXSLOT) {
        int b = idx / (4 * HWSZ);
        int rem = idx - b * 4 * HWSZ;
        int q = rem / HWSZ;
        int pix = rem - q * HWSZ;
        uint2 u; u.x = 0; u.y = 0;
        if (q == 0)
            u.x = h2bits(xsrc[(size_t)b * 2 * HWSZ + pix],
                         xsrc[(size_t)(b * 2 + 1) * HWSZ + pix]);
        xdst[idx] = u;
        return;
    }
    int wk = idx - NXSLOT;
    if (wk >= NWSLOT) return;

    if (wk < 57600) {
        // layers 0..6 (conv stack), [chunk][tap][co64][q]
        const float* tbl[7] = {w0, w1, w2, w3, w4, w5, w6};
        int L, c, slot, CIN, COUT;
        if (wk < 2304) { L = 0; c = 0; slot = wk; CIN = 2; COUT = NFC; }
        else {
            int r = wk - 2304;
            L = 1 + r / 9216;
            int r2 = r - (L - 1) * 9216;
            c = r2 / 2304;
            slot = r2 - c * 2304;
            CIN = NFC; COUT = NFC;
        }
        const float* wgt = tbl[L];
        int tap = slot >> 8, co = (slot >> 2) & 63, q = slot & 3;
        int c0 = c * 16 + 2 * q;
        float f0 = 0.f, f1 = 0.f, f2 = 0.f, f3 = 0.f;
        if (co < COUT) {
            if (c0 < CIN)     f0 = wgt[((size_t)co * CIN + c0) * 9 + tap];
            if (c0 + 1 < CIN) f1 = wgt[((size_t)co * CIN + c0 + 1) * 9 + tap];
            if (c0 + 8 < CIN) f2 = wgt[((size_t)co * CIN + c0 + 8) * 9 + tap];
            if (c0 + 9 < CIN) f3 = wgt[((size_t)co * CIN + c0 + 9) * 9 + tap];
        }
        uint2 u; u.x = h2bits(f0, f1); u.y = h2bits(f2, f3);
        wp[wk] = u;
    } else {
        // fused out-conv: [chunk][tap][co40][q]
        int rem = wk - 57600;
        int c = rem / 1440;
        int slot = rem - c * 1440;
        int tap = slot / 160;
        int r2 = slot - tap * 160;
        int co = r2 >> 2, q = r2 & 3;
        int c0 = c * 16 + 2 * q;
        float f0 = 0.f, f1 = 0.f, f2 = 0.f, f3 = 0.f;
        if (co < COUTF) {
            f0 = w7[((size_t)co * NFC + c0) * 9 + tap];
            f1 = w7[((size_t)co * NFC + c0 + 1) * 9 + tap];
            f2 = w7[((size_t)co * NFC + c0 + 8) * 9 + tap];
            f3 = w7[((size_t)co * NFC + c0 + 9) * 9 + tap];
        }
        uint2 u; u.x = h2bits(f0, f1); u.y = h2bits(f2, f3);
        wp[wk] = u;
    }
}

// ---------------------------------------------------------------------------
// 3x3 conv as implicit GEMM, fp16 m16n8k16, cp.async double-buffered.
// (Unchanged from R13 winning config; only PACKOUT=true used.)
// ---------------------------------------------------------------------------
template<int CIN, bool RELU, bool RESID>
__global__ __launch_bounds__(512, 1)
void conv_mma(const uint2* __restrict__ in, const uint4* __restrict__ wsrc,
              const float* __restrict__ bias, const uint2* __restrict__ res,
              uint2* __restrict__ op)
{
    constexpr int CHUNKS = (CIN + 15) / 16;
    extern __shared__ char smem[];
    const uint32_t sbase = smem_u32(smem);

    const int t = threadIdx.x, lane = t & 31, wid = t >> 5;
    const int wm = wid & 7, wn = wid >> 3;
    const int x0 = blockIdx.x * 64, y0 = blockIdx.y * 8, b = blockIdx.z;
    const int gid = lane >> 2, tid4 = lane & 3;

    int xsoff[6], xgoff[6];
    uint32_t xfl = 0;
    #pragma unroll
    for (int s6 = 0; s6 < 6; ++s6) {
        xsoff[s6] = -1; xgoff[s6] = 0;
        int ii = t + 512 * s6;
        if (ii < 2720) {
            int pr = ii / 68, s = ii - pr * 68;
            int p = pr & 3, r = pr >> 2;
            int gy = y0 - 1 + r, gx = x0 + s - 1;
            if (s < 66) {
                xsoff[s6] = p * 684 + r * 68 + s;
                if (gy >= 0 && gy < HH && gx >= 0 && gx < WW) {
                    xgoff[s6] = p * HWSZ + gy * WW + gx;
                    xfl |= 1u << s6;
                }
            }
        }
    }

    float acc[4][4][4];
    #pragma unroll
    for (int mt = 0; mt < 4; ++mt)
        #pragma unroll
        for (int nt = 0; nt < 4; ++nt)
            #pragma unroll
            for (int k = 0; k < 4; ++k) acc[mt][nt][k] = 0.f;

    const int abase = tid4 * 684 + wm * 68 + gid;
    const int bbase = (wn * 32 + gid) * 4 + tid4;
    const uint2* inb_p = in + (size_t)b * CHUNKS * 4 * HWSZ;

    auto prefetch = [&](int c) {
        const uint32_t xb = sbase + (c & 1) * 21888;
        const uint2* inc = inb_p + (size_t)c * 4 * HWSZ;
        #pragma unroll
        for (int s6 = 0; s6 < 6; ++s6) {
            int so = xsoff[s6];
            if (so >= 0) {
                int n = (xfl >> s6) & 1 ? 8 : 0;
                cpa8(xb + so * 8, inc + xgoff[s6], n);
            }
        }
        const uint32_t wbse = sbase + 43776 + (c & 1) * 18432;
        const uint4* ws = wsrc + (size_t)c * 1152;
        #pragma unroll
        for (int s3 = 0; s3 < 3; ++s3) {
            int i = t + 512 * s3;
            if (i < 1152) cpa16(wbse + i * 16, ws + i);
        }
        CPA_COMMIT();
    };

    prefetch(0);
    for (int c = 0; c < CHUNKS; ++c) {
        CPA_WAIT0();
        __syncthreads();
        if (c + 1 < CHUNKS) prefetch(c + 1);
        const uint2* sX2 = (const uint2*)(smem + (c & 1) * 21888);
        const uint2* sW2 = (const uint2*)(smem + 43776 + (c & 1) * 18432);

        #pragma unroll
        for (int tap = 0; tap < 9; ++tap) {
            const int dy = tap / 3, dx = tap - dy * 3;
            uint2 bf[4];
            #pragma unroll
            for (int nt = 0; nt < 4; ++nt)
                bf[nt] = sW2[tap * 256 + nt * 32 + bbase];
            #pragma unroll
            for (int mt = 0; mt < 4; ++mt) {
                uint2 u = sX2[abase + dy * 68 + dx + mt * 16];
                uint2 v = sX2[abase + dy * 68 + dx + mt * 16 + 8];
                #pragma unroll
                for (int nt = 0; nt < 4; ++nt)
                    mma_f16(acc[mt][nt], u.x, v.x, u.y, v.y, bf[nt].x, bf[nt].y);
            }
        }
    }

    const int y = y0 + wm;
    #pragma unroll
    for (int cq = 0; cq < 2; ++cq) {
        int cb = wn * 32 + 16 * cq + 2 * tid4;
        float bx0 = bias[cb], bx1 = bias[cb + 1];
        float by0 = bias[cb + 8], by1 = bias[cb + 9];
        size_t plane = (((size_t)b * 4 + wn * 2 + cq) * 4 + tid4) * HWSZ + (size_t)y * WW;
        #pragma unroll
        for (int mt = 0; mt < 4; ++mt) {
            #pragma unroll
            for (int h8 = 0; h8 < 2; ++h8) {
                int x = x0 + mt * 16 + gid + h8 * 8;
                float vx0 = acc[mt][2 * cq][h8 * 2 + 0] + bx0;
                float vx1 = acc[mt][2 * cq][h8 * 2 + 1] + bx1;
                float vy0 = acc[mt][2 * cq + 1][h8 * 2 + 0] + by0;
                float vy1 = acc[mt][2 * cq + 1][h8 * 2 + 1] + by1;
                if (RELU) {
                    vx0 = fmaxf(vx0, 0.f); vx1 = fmaxf(vx1, 0.f);
                    vy0 = fmaxf(vy0, 0.f); vy1 = fmaxf(vy1, 0.f);
                }
                size_t oi = plane + x;
                if (RESID) {
                    uint2 r = res[oi];
                    float2 lo = h2f(r.x), hi = h2f(r.y);
                    vx0 += lo.x; vx1 += lo.y; vy0 += hi.x; vy1 += hi.y;
                }
                uint2 o; o.x = h2bits(vx0, vx1); o.y = h2bits(vy0, vy1);
                op[oi] = o;
            }
        }
    }
}

// ---------------- KPN tables ----------------
#define FST 33
#define FTH 30

struct TEnt { int lo, hi, doff; bool inR; float a, b; };

__host__ __device__ constexpr double csqrt_(double x) {
    double g = x > 1.0 ? x : 1.0;
    for (int i = 0; i < 100; ++i) g = 0.5 * (g + x / g);
    return g;
}
__host__ __device__ constexpr TEnt tentry(int w, int p) {
    const int K = 2 * w - 1, r = w - 1, coff = w * (w - 1) / 2 - 1;
    const int i = p / K, j = p % K;
    TEnt e{};
    e.doff = (i - r) * FST + (j - r);
    const int s2 = (i - r) * (i - r) + (j - r) * (j - r);
    int q = 0;
    while ((q + 1) * (q + 1) <= s2) ++q;
    if (q * q == s2) {
        if (q > r) { e.inR = false; e.lo = coff; e.hi = coff; e.a = 0.f; e.b = 0.f; }
        else       { e.inR = true;  e.lo = coff + q; e.hi = coff + q; e.a = 1.f; e.b = 0.f; }
    } else {
        if (q >= r) { e.inR = false; e.lo = coff; e.hi = coff; e.a = 0.f; e.b = 0.f; }
        else {
            double d = csqrt_((double)s2);
            e.inR = true; e.lo = coff + q; e.hi = coff + q + 1;
            e.a = (float)((double)(q + 1) - d);
            e.b = (float)(d - (double)q);
        }
    }
    return e;
}

template<int W, int Lo, int N>
struct KLoop {
    static __device__ __forceinline__ void run(const float (&c)[COUTF], const float* __restrict__ sF,
                                               int ctr, float& den, float& num) {
        KLoop<W, Lo, N / 2>::run(c, sF, ctr, den, num);
        KLoop<W, Lo + N / 2, N - N / 2>::run(c, sF, ctr, den, num);
    }
};
template<int W, int Lo>
struct KLoop<W, Lo, 1> {
    static __device__ __forceinline__ void run(const float (&c)[COUTF], const float* __restrict__ sF,
                                               int ctr, float& den, float& num) {
        constexpr TEnt e = tentry(W, Lo);
        float patch = sF[ctr + e.doff];
        if constexpr (e.inR) {
            float v = e.a * c[e.lo] + e.b * c[e.hi];
            float tt = __expf(v);
            den += tt; num += tt * patch;
        } else { den += 1.f; num += patch; }
    }
};
template<int W, int Lo>
struct KLoop<W, Lo, 0> {
    static __device__ __forceinline__ void run(const float (&)[COUTF], const float* __restrict__,
                                               int, float&, float&) {}
};

template<int W>
__device__ __forceinline__ float section_run(const float (&c)[COUTF], const float* __restrict__ sF, int ctr) {
    constexpr int K = 2 * W - 1;
    float den = 0.f, num = 0.f;
    KLoop<W, 0, K * K>::run(c, sF, ctr, den, num);
    return num / den;
}

// ---------------------------------------------------------------------------
// FUSED out-conv (64 -> 35, padded to 40) + KPN aggregation.
// Block: 16x16 px tile, 256 thr = 8 warps. m-tile = one y-row (16 px),
// warp w -> rows {2w, 2w+1}; nt = 5 n8-tiles (40 co).
// X smem: 4 q-planes x 18x18, plane stride 332 uint2 (332%16==12 -> CF).
// W smem: [tap][co40][q] uint2. sCore: [256 px][stride 37] f32 (CF reads).
// smem map: X 2x10624 @0, W 2x11520 @21248, sCore 37888 @44288, sF @82176.
// ---------------------------------------------------------------------------
__global__ __launch_bounds__(256)
void kpn_fused(const uint2* __restrict__ hA, const uint4* __restrict__ wsrc,
               const float* __restrict__ bias, const float* __restrict__ data,
               float* __restrict__ out)
{
    extern __shared__ char smem[];
    const uint32_t sbase = smem_u32(smem);
    float* sCore = (float*)(smem + 44288);
    float* sF    = (float*)(smem + 82176);

    const int t = threadIdx.x, lane = t & 31, wid = t >> 5;
    const int gid = lane >> 2, tid4 = lane & 3;
    const int x0 = blockIdx.x * 16, y0 = blockIdx.y * 16, b = blockIdx.z;

    // stage frame tile (for KPN patches)
    {
        const int oy = y0 - 7, ox = x0 - 7;
        for (int idx = t; idx < FTH * FTH; idx += 256) {
            int fy = idx / FTH, fx = idx - fy * FTH;
            int gy = oy + fy, gx = ox + fx;
            float v = 0.f;
            if (gy >= 0 && gy < HH && gx >= 0 && gx < WW)
                v = data[((size_t)b * HH + gy) * WW + gx];
            sF[fy * FST + fx] = v;
        }
    }

    // X staging slots: 1296 = 4q x 18r x 18s
    int xsoff[6], xgoff[6];
    uint32_t xfl = 0;
    #pragma unroll
    for (int s6 = 0; s6 < 6; ++s6) {
        xsoff[s6] = -1; xgoff[s6] = 0;
        int ii = t + 256 * s6;
        if (ii < 1296) {
            int q = ii / 324, rm = ii - q * 324, r = rm / 18, s = rm - r * 18;
            int gy = y0 - 1 + r, gx = x0 - 1 + s;
            xsoff[s6] = q * 332 + r * 18 + s;
            if (gy >= 0 && gy < HH && gx >= 0 && gx < WW) {
                xgoff[s6] = q * HWSZ + gy * WW + gx;
                xfl |= 1u << s6;
            }
        }
    }

    const uint2* inb_p = hA + (size_t)b * 16 * HWSZ;
    auto prefetch = [&](int c) {
        const uint32_t xb = sbase + (c & 1) * 10624;
        const uint2* inc = inb_p + (size_t)c * 4 * HWSZ;
        #pragma unroll
        for (int s6 = 0; s6 < 6; ++s6) {
            int so = xsoff[s6];
            if (so >= 0) {
                int n = (xfl >> s6) & 1 ? 8 : 0;
                cpa8(xb + so * 8, inc + xgoff[s6], n);
            }
        }
        const uint32_t wbse = sbase + 21248 + (c & 1) * 11520;
        const uint4* ws = wsrc + (size_t)c * 720;
        #pragma unroll
        for (int s3 = 0; s3 < 3; ++s3) {
            int i = t + 256 * s3;
            if (i < 720) cpa16(wbse + i * 16, ws + i);
        }
        CPA_COMMIT();
    };

    float acc[2][5][4];
    #pragma unroll
    for (int mt = 0; mt < 2; ++mt)
        #pragma unroll
        for (int nt = 0; nt < 5; ++nt)
            #pragma unroll
            for (int k = 0; k < 4; ++k) acc[mt][nt][k] = 0.f;

    const int bbase = gid * 4 + tid4;

    prefetch(0);
    for (int c = 0; c < 4; ++c) {
        CPA_WAIT0();
        __syncthreads();
        if (c + 1 < 4) prefetch(c + 1);
        const uint2* sX2 = (const uint2*)(smem + (c & 1) * 10624);
        const uint2* sW2 = (const uint2*)(smem + 21248 + (c & 1) * 11520);

        #pragma unroll
        for (int tap = 0; tap < 9; ++tap) {
            const int dy = tap / 3, dx = tap - dy * 3;
            uint2 bf[5];
            #pragma unroll
            for (int nt = 0; nt < 5; ++nt)
                bf[nt] = sW2[tap * 160 + nt * 32 + bbase];
            #pragma unroll
            for (int mt = 0; mt < 2; ++mt) {
                int yw = 2 * wid + mt;
                uint2 u = sX2[tid4 * 332 + (yw + dy) * 18 + gid + dx];
                uint2 v = sX2[tid4 * 332 + (yw + dy) * 18 + gid + dx + 8];
                #pragma unroll
                for (int nt = 0; nt < 5; ++nt)
                    mma_f16(acc[mt][nt], u.x, v.x, u.y, v.y, bf[nt].x, bf[nt].y);
            }
        }
    }

    // scatter accumulators to sCore (guard co < 35), add bias
    #pragma unroll
    for (int nt = 0; nt < 5; ++nt) {
        int co0 = nt * 8 + 2 * tid4, co1 = co0 + 1;
        float bv0 = (co0 < COUTF) ? bias[co0] : 0.f;
        float bv1 = (co1 < COUTF) ? bias[co1] : 0.f;
        #pragma unroll
        for (int mt = 0; mt < 2; ++mt) {
            int yw = 2 * wid + mt;
            int px0 = yw * 16 + gid, px1 = px0 + 8;
            if (co0 < COUTF) {
                sCore[px0 * 37 + co0] = acc[mt][nt][0] + bv0;
                sCore[px1 * 37 + co0] = acc[mt][nt][2] + bv0;
            }
            if (co1 < COUTF) {
                sCore[px0 * 37 + co1] = acc[mt][nt][1] + bv1;
                sCore[px1 * 37 + co1] = acc[mt][nt][3] + bv1;
            }
        }
    }
    __syncthreads();

    // per-pixel KPN
    const int tx = t & 15, ty = t >> 4;
    const int px = ty * 16 + tx;
    float c[COUTF];
    #pragma unroll
    for (int ch = 0; ch < COUTF; ++ch)
        c[ch] = fabsf(sCore[px * 37 + ch]);

    const int ctr = (ty + 7) * FST + (tx + 7);
    float pred = 0.f;
    pred += section_run<2>(c, sF, ctr);
    pred += section_run<3>(c, sF, ctr);
    pred += section_run<4>(c, sF, ctr);
    pred += section_run<5>(c, sF, ctr);
    pred += section_run<6>(c, sF, ctr);
    pred += section_run<7>(c, sF, ctr);
    pred += section_run<8>(c, sF, ctr);

    out[((size_t)b * HH + y0 + ty) * WW + x0 + tx] = pred;
}

// ------------------------------- launch --------------------------------------
#define SMEMSZ 80640
#define FSMEM  86136

extern "C" void kernel_launch(void* const* d_in, const int* in_sizes, int n_in,
                              void* d_out, int out_size) {
    (void)in_sizes; (void)n_in; (void)out_size;
    const float* data_with_est = (const float*)d_in[0];
    const float* data  = (const float*)d_in[1];
    const float* w_first = (const float*)d_in[2];
    const float* b_first = (const float*)d_in[3];
    const float* w1a = (const float*)d_in[4];
    const float* b1a = (const float*)d_in[5];
    const float* w1b = (const float*)d_in[6];
    const float* b1b = (const float*)d_in[7];
    const float* w2a = (const float*)d_in[8];
    const float* b2a = (const float*)d_in[9];
    const float* w2b = (const float*)d_in[10];
    const float* b2b = (const float*)d_in[11];
    const float* w3a = (const float*)d_in[12];
    const float* b3a = (const float*)d_in[13];
    const float* w3b = (const float*)d_in[14];
    const float* b3b = (const float*)d_in[15];
    const float* w_out = (const float*)d_in[16];
    const float* b_out = (const float*)d_in[17];
    float* out = (float*)d_out;

    uint2 *hA = nullptr, *hB = nullptr, *xin = nullptr, *wp = nullptr;
    cudaGetSymbolAddress((void**)&hA, g_hA);
    cudaGetSymbolAddress((void**)&hB, g_hB);
    cudaGetSymbolAddress((void**)&xin, g_xin);
    cudaGetSymbolAddress((void**)&wp, g_wpack);

    const size_t o0 = 0, o1 = 2304, o2 = 11520, o3 = 20736,
                 o4 = 29952, o5 = 39168, o6 = 48384, oF = 57600;

    cudaFuncSetAttribute(conv_mma<2, false, false>, cudaFuncAttributeMaxDynamicSharedMemorySize, SMEMSZ);
    cudaFuncSetAttribute(conv_mma<NFC, true, false>, cudaFuncAttributeMaxDynamicSharedMemorySize, SMEMSZ);
    cudaFuncSetAttribute(conv_mma<NFC, false, true>, cudaFuncAttributeMaxDynamicSharedMemorySize, SMEMSZ);
    cudaFuncSetAttribute(kpn_fused, cudaFuncAttributeMaxDynamicSharedMemorySize, FSMEM);

    prepass<<<(NXSLOT + NWSLOT + 255) / 256, 256>>>(
        data_with_est, xin, w_first, w1a, w1b, w2a, w2b, w3a, w3b, w_out, wp);

    dim3 grid(WW / 64, HH / 8, BB), blk(512);

    conv_mma<2, false, false><<<grid, blk, SMEMSZ>>>(xin, (const uint4*)(wp + o0), b_first, nullptr, hA);
    conv_mma<NFC, true,  false><<<grid, blk, SMEMSZ>>>(hA, (const uint4*)(wp + o1), b1a, nullptr, hB);
    conv_mma<NFC, false, true ><<<grid, blk, SMEMSZ>>>(hB, (const uint4*)(wp + o2), b1b, hA, hA);
    conv_mma<NFC, true,  false><<<grid, blk, SMEMSZ>>>(hA, (const uint4*)(wp + o3), b2a, nullptr, hB);
    conv_mma<NFC, false, true ><<<grid, blk, SMEMSZ>>>(hB, (const uint4*)(wp + o4), b2b, hA, hA);
    conv_mma<NFC, true,  false><<<grid, blk, SMEMSZ>>>(hA, (const uint4*)(wp + o5), b3a, nullptr, hB);
    conv_mma<NFC, false, true ><<<grid, blk, SMEMSZ>>>(hB, (const uint4*)(wp + o6), b3b, hA, hA);

    kpn_fused<<<dim3(WW / 16, HH / 16, BB), 256, FSMEM>>>(
        hA, (const uint4*)(wp + oF), b_out, data, out);
}

// round 16
// speedup vs baseline: 2.0032x; 1.0287x over previous
#include <cuda_runtime.h>
#include <cuda_fp16.h>
#include <cstdint>
#include <cstddef>

#define HH 384
#define WW 384
#define BB 2
#define NFC 64
#define COUTF 35
#define HWSZ (HH * WW)
#define NXSLOT (BB * 4 * HWSZ)
#define NWSLOT 65664   // 4608 + 6*9216 + 5760

__device__ uint2 g_hA[(size_t)BB * 16 * HWSZ];
__device__ uint2 g_hB[(size_t)BB * 16 * HWSZ];
__device__ uint2 g_xin[(size_t)BB * 4 * HWSZ];
__device__ uint2 g_wpack[NWSLOT];

__device__ __forceinline__ uint32_t smem_u32(const void* p) {
    uint32_t a;
    asm("{ .reg .u64 t; cvta.to.shared.u64 t, %1; cvt.u32.u64 %0, t; }" : "=r"(a) : "l"(p));
    return a;
}
__device__ __forceinline__ void cpa8(uint32_t sa, const void* g, int n) {
    asm volatile("cp.async.ca.shared.global [%0], [%1], 8, %2;" :: "r"(sa), "l"(g), "r"(n));
}
__device__ __forceinline__ void cpa16(uint32_t sa, const void* g) {
    asm volatile("cp.async.cg.shared.global [%0], [%1], 16;" :: "r"(sa), "l"(g));
}
#define CPA_COMMIT() asm volatile("cp.async.commit_group;" ::: "memory")
#define CPA_WAIT0()  asm volatile("cp.async.wait_group 0;" ::: "memory")
#define CPA_WAIT1()  asm volatile("cp.async.wait_group 1;" ::: "memory")

__device__ __forceinline__ void mma_f16(float* d, uint32_t a0, uint32_t a1,
                                        uint32_t a2, uint32_t a3,
                                        uint32_t b0, uint32_t b1) {
    asm volatile("mma.sync.aligned.m16n8k16.row.col.f32.f16.f16.f32 "
                 "{%0,%1,%2,%3}, {%4,%5,%6,%7}, {%8,%9}, {%0,%1,%2,%3};"
                 : "+f"(d[0]), "+f"(d[1]), "+f"(d[2]), "+f"(d[3])
                 : "r"(a0), "r"(a1), "r"(a2), "r"(a3), "r"(b0), "r"(b1));
}
__device__ __forceinline__ uint32_t h2bits(float a, float b) {
    __half2 h = __floats2half2_rn(a, b);
    return *(uint32_t*)&h;
}
__device__ __forceinline__ float2 h2f(uint32_t u) {
    return __half22float2(*(__half2*)&u);
}

// ---------------- fused prepass: pack input + ALL weights to fp16 ------------
// Conv layers 0..6: [c32][tap][co64][j8] uint2; j -> g = c32*2 + (j>>2), q = j&3.
// Fused out-conv:   [c16][tap][co40][q4] uint2 (kpn_fused layout).
__global__ void prepass(const float* __restrict__ xsrc, uint2* __restrict__ xdst,
                        const float* __restrict__ w0, const float* __restrict__ w1,
                        const float* __restrict__ w2, const float* __restrict__ w3,
                        const float* __restrict__ w4, const float* __restrict__ w5,
                        const float* __restrict__ w6, const float* __restrict__ w7,
                        uint2* __restrict__ wp)
{
    int idx = blockIdx.x * 256 + threadIdx.x;
    if (idx < NXSLOT) {
        int b = idx / (4 * HWSZ);
        int rem = idx - b * 4 * HWSZ;
        int q = rem / HWSZ;
        int pix = rem - q * HWSZ;
        uint2 u; u.x = 0; u.y = 0;
        if (q == 0)
            u.x = h2bits(xsrc[(size_t)b * 2 * HWSZ + pix],
                         xsrc[(size_t)(b * 2 + 1) * HWSZ + pix]);
        xdst[idx] = u;
        return;
    }
    int wk = idx - NXSLOT;
    if (wk >= NWSLOT) return;

    if (wk < 59904) {
        const float* tbl[7] = {w0, w1, w2, w3, w4, w5, w6};
        int L, c32, slot, CIN;
        if (wk < 4608) { L = 0; c32 = 0; slot = wk; CIN = 2; }
        else {
            int r = wk - 4608;
            L = 1 + r / 9216;
            int r2 = r - (L - 1) * 9216;
            c32 = r2 / 4608;
            slot = r2 - c32 * 4608;
            CIN = NFC;
        }
        const float* wgt = tbl[L];
        int tap = slot >> 9, rr = slot & 511, co = rr >> 3, j = rr & 7;
        int g = c32 * 2 + (j >> 2), q = j & 3;
        int c0 = g * 16 + 2 * q;
        float f0 = 0.f, f1 = 0.f, f2 = 0.f, f3 = 0.f;
        if (c0 < CIN)     f0 = wgt[((size_t)co * CIN + c0) * 9 + tap];
        if (c0 + 1 < CIN) f1 = wgt[((size_t)co * CIN + c0 + 1) * 9 + tap];
        if (c0 + 8 < CIN) f2 = wgt[((size_t)co * CIN + c0 + 8) * 9 + tap];
        if (c0 + 9 < CIN) f3 = wgt[((size_t)co * CIN + c0 + 9) * 9 + tap];
        uint2 u; u.x = h2bits(f0, f1); u.y = h2bits(f2, f3);
        wp[wk] = u;
    } else {
        int rem = wk - 59904;
        int c = rem / 1440;
        int slot = rem - c * 1440;
        int tap = slot / 160;
        int r2 = slot - tap * 160;
        int co = r2 >> 2, q = r2 & 3;
        int c0 = c * 16 + 2 * q;
        float f0 = 0.f, f1 = 0.f, f2 = 0.f, f3 = 0.f;
        if (co < COUTF) {
            f0 = w7[((size_t)co * NFC + c0) * 9 + tap];
            f1 = w7[((size_t)co * NFC + c0 + 1) * 9 + tap];
            f2 = w7[((size_t)co * NFC + c0 + 8) * 9 + tap];
            f3 = w7[((size_t)co * NFC + c0 + 9) * 9 + tap];
        }
        uint2 u; u.x = h2bits(f0, f1); u.y = h2bits(f2, f3);
        wp[wk] = u;
    }
}

// ---------------------------------------------------------------------------
// 3x3 conv as implicit GEMM, fp16 m16n8k16, 32-channel K-chunks, BOTH chunks
// fully prefetched up-front (disjoint buffers -> only 2 wait+sync points).
// Tile 64 px x 8 rows x 64 co; 512 thr = 16 warps (wm 0..7, wn 0..1),
// warp tile mt=4 x nt=4 x 2 k-halves.
// X smem: per chunk 8 planes x (10r x 68c), plane stride 684 uint2 (CF).
// W smem: per chunk [tap][co64][q8 pad12] uint2, co stride 12 (CF).
// smem: X 2x43776 @0, W 2x55296 @87552 = 198144B, 1 block/SM.
// ---------------------------------------------------------------------------
template<int CIN, bool RELU, bool RESID>
__global__ __launch_bounds__(512, 1)
void conv_mma(const uint2* __restrict__ in, const uint4* __restrict__ wsrc,
              const float* __restrict__ bias, const uint2* __restrict__ res,
              uint2* __restrict__ op)
{
    constexpr int CH32 = (CIN + 31) / 32;
    constexpr int PLG  = (CIN == 2) ? 4 : 8;   // valid global planes per chunk
    constexpr int PLB  = (CIN == 2) ? 4 : 16;  // planes per batch in global buffer
    extern __shared__ char smem[];
    const uint32_t sbase = smem_u32(smem);

    const int t = threadIdx.x, lane = t & 31, wid = t >> 5;
    const int wm = wid & 7, wn = wid >> 3;
    const int x0 = blockIdx.x * 64, y0 = blockIdx.y * 8, b = blockIdx.z;
    const int gid = lane >> 2, tid4 = lane & 3;

    // X staging slots: 5440 = 8p x 10r x 68s -> 11 per thread
    int xsoff[11], xgoff[11];
    uint32_t xfl = 0;
    #pragma unroll
    for (int s = 0; s < 11; ++s) {
        xsoff[s] = -1; xgoff[s] = 0;
        int ii = t + 512 * s;
        if (ii < 5440) {
            int pr = ii / 68, sc = ii - pr * 68;
            int p = pr & 7, r = pr >> 3;
            int gy = y0 - 1 + r, gx = x0 + sc - 1;
            if (sc < 66) {
                xsoff[s] = p * 684 + r * 68 + sc;
                if (p < PLG && gy >= 0 && gy < HH && gx >= 0 && gx < WW) {
                    xgoff[s] = p * HWSZ + gy * WW + gx;
                    xfl |= 1u << s;
                }
            }
        }
    }

    float acc[4][4][4];
    #pragma unroll
    for (int mt = 0; mt < 4; ++mt)
        #pragma unroll
        for (int nt = 0; nt < 4; ++nt)
            #pragma unroll
            for (int k = 0; k < 4; ++k) acc[mt][nt][k] = 0.f;

    const int abase = tid4 * 684 + wm * 68 + gid;
    const uint2* inb_p = in + (size_t)b * PLB * HWSZ;

    auto prefetch = [&](int c) {
        const uint32_t xb = sbase + c * 43776;
        const uint2* inc = inb_p + (size_t)c * 8 * HWSZ;
        #pragma unroll
        for (int s = 0; s < 11; ++s) {
            int so = xsoff[s];
            if (so >= 0) {
                int n = (xfl >> s) & 1 ? 8 : 0;
                cpa8(xb + so * 8, inc + xgoff[s], n);
            }
        }
        const uint32_t wbse = sbase + 87552 + c * 55296;
        const uint4* ws = wsrc + (size_t)c * 2304;
        #pragma unroll
        for (int s5 = 0; s5 < 5; ++s5) {
            int i = t + 512 * s5;
            if (i < 2304) {
                int tap = i >> 8, r = i & 255, co = r >> 2, qp = r & 3;
                cpa16(wbse + (tap * 768 + co * 12 + qp * 2) * 8, ws + i);
            }
        }
        CPA_COMMIT();
    };

    auto compute = [&](int c) {
        const uint2* sX = (const uint2*)(smem + c * 43776);
        const uint2* sW = (const uint2*)(smem + 87552 + c * 55296);
        #pragma unroll
        for (int tap = 0; tap < 9; ++tap) {
            const int dy = tap / 3, dx = tap - dy * 3;
            uint2 bf0[4], bf1[4];
            #pragma unroll
            for (int nt = 0; nt < 4; ++nt) {
                int wb = tap * 768 + (wn * 32 + nt * 8 + gid) * 12 + tid4;
                bf0[nt] = sW[wb];
                if (CIN > 16) bf1[nt] = sW[wb + 4];
            }
            #pragma unroll
            for (int mt = 0; mt < 4; ++mt) {
                int ab = abase + dy * 68 + dx + mt * 16;
                uint2 u0 = sX[ab], v0 = sX[ab + 8];
                #pragma unroll
                for (int nt = 0; nt < 4; ++nt)
                    mma_f16(acc[mt][nt], u0.x, v0.x, u0.y, v0.y, bf0[nt].x, bf0[nt].y);
                if (CIN > 16) {
                    uint2 u1 = sX[ab + 2736], v1 = sX[ab + 2744];
                    #pragma unroll
                    for (int nt = 0; nt < 4; ++nt)
                        mma_f16(acc[mt][nt], u1.x, v1.x, u1.y, v1.y, bf1[nt].x, bf1[nt].y);
                }
            }
        }
    };

    if (CH32 == 2) {
        prefetch(0);
        prefetch(1);
        CPA_WAIT1();
        __syncthreads();
        compute(0);
        CPA_WAIT0();
        __syncthreads();
        compute(1);
    } else {
        prefetch(0);
        CPA_WAIT0();
        __syncthreads();
        compute(0);
    }

    const int y = y0 + wm;
    #pragma unroll
    for (int cq = 0; cq < 2; ++cq) {
        int cb = wn * 32 + 16 * cq + 2 * tid4;
        float bx0 = bias[cb], bx1 = bias[cb + 1];
        float by0 = bias[cb + 8], by1 = bias[cb + 9];
        size_t plane = (((size_t)b * 4 + wn * 2 + cq) * 4 + tid4) * HWSZ + (size_t)y * WW;
        #pragma unroll
        for (int mt = 0; mt < 4; ++mt) {
            #pragma unroll
            for (int h8 = 0; h8 < 2; ++h8) {
                int x = x0 + mt * 16 + gid + h8 * 8;
                float vx0 = acc[mt][2 * cq][h8 * 2 + 0] + bx0;
                float vx1 = acc[mt][2 * cq][h8 * 2 + 1] + bx1;
                float vy0 = acc[mt][2 * cq + 1][h8 * 2 + 0] + by0;
                float vy1 = acc[mt][2 * cq + 1][h8 * 2 + 1] + by1;
                if (RELU) {
                    vx0 = fmaxf(vx0, 0.f); vx1 = fmaxf(vx1, 0.f);
                    vy0 = fmaxf(vy0, 0.f); vy1 = fmaxf(vy1, 0.f);
                }
                size_t oi = plane + x;
                if (RESID) {
                    uint2 r = res[oi];
                    float2 lo = h2f(r.x), hi = h2f(r.y);
                    vx0 += lo.x; vx1 += lo.y; vy0 += hi.x; vy1 += hi.y;
                }
                uint2 o; o.x = h2bits(vx0, vx1); o.y = h2bits(vy0, vy1);
                op[oi] = o;
            }
        }
    }
}

// ---------------- KPN tables ----------------
#define FST 33
#define FTH 30

struct TEnt { int lo, hi, doff; bool inR; float a, b; };

__host__ __device__ constexpr double csqrt_(double x) {
    double g = x > 1.0 ? x : 1.0;
    for (int i = 0; i < 100; ++i) g = 0.5 * (g + x / g);
    return g;
}
__host__ __device__ constexpr TEnt tentry(int w, int p) {
    const int K = 2 * w - 1, r = w - 1, coff = w * (w - 1) / 2 - 1;
    const int i = p / K, j = p % K;
    TEnt e{};
    e.doff = (i - r) * FST + (j - r);
    const int s2 = (i - r) * (i - r) + (j - r) * (j - r);
    int q = 0;
    while ((q + 1) * (q + 1) <= s2) ++q;
    if (q * q == s2) {
        if (q > r) { e.inR = false; e.lo = coff; e.hi = coff; e.a = 0.f; e.b = 0.f; }
        else       { e.inR = true;  e.lo = coff + q; e.hi = coff + q; e.a = 1.f; e.b = 0.f; }
    } else {
        if (q >= r) { e.inR = false; e.lo = coff; e.hi = coff; e.a = 0.f; e.b = 0.f; }
        else {
            double d = csqrt_((double)s2);
            e.inR = true; e.lo = coff + q; e.hi = coff + q + 1;
            e.a = (float)((double)(q + 1) - d);
            e.b = (float)(d - (double)q);
        }
    }
    return e;
}

template<int W, int Lo, int N>
struct KLoop {
    static __device__ __forceinline__ void run(const float (&c)[COUTF], const float* __restrict__ sF,
                                               int ctr, float& den, float& num) {
        KLoop<W, Lo, N / 2>::run(c, sF, ctr, den, num);
        KLoop<W, Lo + N / 2, N - N / 2>::run(c, sF, ctr, den, num);
    }
};
template<int W, int Lo>
struct KLoop<W, Lo, 1> {
    static __device__ __forceinline__ void run(const float (&c)[COUTF], const float* __restrict__ sF,
                                               int ctr, float& den, float& num) {
        constexpr TEnt e = tentry(W, Lo);
        float patch = sF[ctr + e.doff];
        if constexpr (e.inR) {
            float v = e.a * c[e.lo] + e.b * c[e.hi];
            float tt = __expf(v);
            den += tt; num += tt * patch;
        } else { den += 1.f; num += patch; }
    }
};
template<int W, int Lo>
struct KLoop<W, Lo, 0> {
    static __device__ __forceinline__ void run(const float (&)[COUTF], const float* __restrict__,
                                               int, float&, float&) {}
};

template<int W>
__device__ __forceinline__ float section_run(const float (&c)[COUTF], const float* __restrict__ sF, int ctr) {
    constexpr int K = 2 * W - 1;
    float den = 0.f, num = 0.f;
    KLoop<W, 0, K * K>::run(c, sF, ctr, den, num);
    return num / den;
}

// ---------------------------------------------------------------------------
// FUSED out-conv (64 -> 35, padded to 40) + KPN aggregation. (As R14.)
// ---------------------------------------------------------------------------
__global__ __launch_bounds__(256)
void kpn_fused(const uint2* __restrict__ hA, const uint4* __restrict__ wsrc,
               const float* __restrict__ bias, const float* __restrict__ data,
               float* __restrict__ out)
{
    extern __shared__ char smem[];
    const uint32_t sbase = smem_u32(smem);
    float* sCore = (float*)(smem + 44288);
    float* sF    = (float*)(smem + 82176);

    const int t = threadIdx.x, lane = t & 31, wid = t >> 5;
    const int gid = lane >> 2, tid4 = lane & 3;
    const int x0 = blockIdx.x * 16, y0 = blockIdx.y * 16, b = blockIdx.z;

    {
        const int oy = y0 - 7, ox = x0 - 7;
        for (int idx = t; idx < FTH * FTH; idx += 256) {
            int fy = idx / FTH, fx = idx - fy * FTH;
            int gy = oy + fy, gx = ox + fx;
            float v = 0.f;
            if (gy >= 0 && gy < HH && gx >= 0 && gx < WW)
                v = data[((size_t)b * HH + gy) * WW + gx];
            sF[fy * FST + fx] = v;
        }
    }

    int xsoff[6], xgoff[6];
    uint32_t xfl = 0;
    #pragma unroll
    for (int s6 = 0; s6 < 6; ++s6) {
        xsoff[s6] = -1; xgoff[s6] = 0;
        int ii = t + 256 * s6;
        if (ii < 1296) {
            int q = ii / 324, rm = ii - q * 324, r = rm / 18, s = rm - r * 18;
            int gy = y0 - 1 + r, gx = x0 - 1 + s;
            xsoff[s6] = q * 332 + r * 18 + s;
            if (gy >= 0 && gy < HH && gx >= 0 && gx < WW) {
                xgoff[s6] = q * HWSZ + gy * WW + gx;
                xfl |= 1u << s6;
            }
        }
    }

    const uint2* inb_p = hA + (size_t)b * 16 * HWSZ;
    auto prefetch = [&](int c) {
        const uint32_t xb = sbase + (c & 1) * 10624;
        const uint2* inc = inb_p + (size_t)c * 4 * HWSZ;
        #pragma unroll
        for (int s6 = 0; s6 < 6; ++s6) {
            int so = xsoff[s6];
            if (so >= 0) {
                int n = (xfl >> s6) & 1 ? 8 : 0;
                cpa8(xb + so * 8, inc + xgoff[s6], n);
            }
        }
        const uint32_t wbse = sbase + 21248 + (c & 1) * 11520;
        const uint4* ws = wsrc + (size_t)c * 720;
        #pragma unroll
        for (int s3 = 0; s3 < 3; ++s3) {
            int i = t + 256 * s3;
            if (i < 720) cpa16(wbse + i * 16, ws + i);
        }
        CPA_COMMIT();
    };

    float acc[2][5][4];
    #pragma unroll
    for (int mt = 0; mt < 2; ++mt)
        #pragma unroll
        for (int nt = 0; nt < 5; ++nt)
            #pragma unroll
            for (int k = 0; k < 4; ++k) acc[mt][nt][k] = 0.f;

    const int bbase = gid * 4 + tid4;

    prefetch(0);
    for (int c = 0; c < 4; ++c) {
        CPA_WAIT0();
        __syncthreads();
        if (c + 1 < 4) prefetch(c + 1);
        const uint2* sX2 = (const uint2*)(smem + (c & 1) * 10624);
        const uint2* sW2 = (const uint2*)(smem + 21248 + (c & 1) * 11520);

        #pragma unroll
        for (int tap = 0; tap < 9; ++tap) {
            const int dy = tap / 3, dx = tap - dy * 3;
            uint2 bf[5];
            #pragma unroll
            for (int nt = 0; nt < 5; ++nt)
                bf[nt] = sW2[tap * 160 + nt * 32 + bbase];
            #pragma unroll
            for (int mt = 0; mt < 2; ++mt) {
                int yw = 2 * wid + mt;
                uint2 u = sX2[tid4 * 332 + (yw + dy) * 18 + gid + dx];
                uint2 v = sX2[tid4 * 332 + (yw + dy) * 18 + gid + dx + 8];
                #pragma unroll
                for (int nt = 0; nt < 5; ++nt)
                    mma_f16(acc[mt][nt], u.x, v.x, u.y, v.y, bf[nt].x, bf[nt].y);
            }
        }
    }

    #pragma unroll
    for (int nt = 0; nt < 5; ++nt) {
        int co0 = nt * 8 + 2 * tid4, co1 = co0 + 1;
        float bv0 = (co0 < COUTF) ? bias[co0] : 0.f;
        float bv1 = (co1 < COUTF) ? bias[co1] : 0.f;
        #pragma unroll
        for (int mt = 0; mt < 2; ++mt) {
            int yw = 2 * wid + mt;
            int px0 = yw * 16 + gid, px1 = px0 + 8;
            if (co0 < COUTF) {
                sCore[px0 * 37 + co0] = acc[mt][nt][0] + bv0;
                sCore[px1 * 37 + co0] = acc[mt][nt][2] + bv0;
            }
            if (co1 < COUTF) {
                sCore[px0 * 37 + co1] = acc[mt][nt][1] + bv1;
                sCore[px1 * 37 + co1] = acc[mt][nt][3] + bv1;
            }
        }
    }
    __syncthreads();

    const int tx = t & 15, ty = t >> 4;
    const int px = ty * 16 + tx;
    float c[COUTF];
    #pragma unroll
    for (int ch = 0; ch < COUTF; ++ch)
        c[ch] = fabsf(sCore[px * 37 + ch]);

    const int ctr = (ty + 7) * FST + (tx + 7);
    float pred = 0.f;
    pred += section_run<2>(c, sF, ctr);
    pred += section_run<3>(c, sF, ctr);
    pred += section_run<4>(c, sF, ctr);
    pred += section_run<5>(c, sF, ctr);
    pred += section_run<6>(c, sF, ctr);
    pred += section_run<7>(c, sF, ctr);
    pred += section_run<8>(c, sF, ctr);

    out[((size_t)b * HH + y0 + ty) * WW + x0 + tx] = pred;
}

// ------------------------------- launch --------------------------------------
#define SMEMSZ 198144
#define FSMEM  86136

extern "C" void kernel_launch(void* const* d_in, const int* in_sizes, int n_in,
                              void* d_out, int out_size) {
    (void)in_sizes; (void)n_in; (void)out_size;
    const float* data_with_est = (const float*)d_in[0];
    const float* data  = (const float*)d_in[1];
    const float* w_first = (const float*)d_in[2];
    const float* b_first = (const float*)d_in[3];
    const float* w1a = (const float*)d_in[4];
    const float* b1a = (const float*)d_in[5];
    const float* w1b = (const float*)d_in[6];
    const float* b1b = (const float*)d_in[7];
    const float* w2a = (const float*)d_in[8];
    const float* b2a = (const float*)d_in[9];
    const float* w2b = (const float*)d_in[10];
    const float* b2b = (const float*)d_in[11];
    const float* w3a = (const float*)d_in[12];
    const float* b3a = (const float*)d_in[13];
    const float* w3b = (const float*)d_in[14];
    const float* b3b = (const float*)d_in[15];
    const float* w_out = (const float*)d_in[16];
    const float* b_out = (const float*)d_in[17];
    float* out = (float*)d_out;

    uint2 *hA = nullptr, *hB = nullptr, *xin = nullptr, *wp = nullptr;
    cudaGetSymbolAddress((void**)&hA, g_hA);
    cudaGetSymbolAddress((void**)&hB, g_hB);
    cudaGetSymbolAddress((void**)&xin, g_xin);
    cudaGetSymbolAddress((void**)&wp, g_wpack);

    const size_t o0 = 0, o1 = 4608, o2 = 13824, o3 = 23040,
                 o4 = 32256, o5 = 41472, o6 = 50688, oF = 59904;

    cudaFuncSetAttribute(conv_mma<2, false, false>, cudaFuncAttributeMaxDynamicSharedMemorySize, SMEMSZ);
    cudaFuncSetAttribute(conv_mma<NFC, true, false>, cudaFuncAttributeMaxDynamicSharedMemorySize, SMEMSZ);
    cudaFuncSetAttribute(conv_mma<NFC, false, true>, cudaFuncAttributeMaxDynamicSharedMemorySize, SMEMSZ);
    cudaFuncSetAttribute(kpn_fused, cudaFuncAttributeMaxDynamicSharedMemorySize, FSMEM);

    prepass<<<(NXSLOT + NWSLOT + 255) / 256, 256>>>(
        data_with_est, xin, w_first, w1a, w1b, w2a, w2b, w3a, w3b, w_out, wp);

    dim3 grid(WW / 64, HH / 8, BB), blk(512);

    conv_mma<2, false, false><<<grid, blk, SMEMSZ>>>(xin, (const uint4*)(wp + o0), b_first, nullptr, hA);
    conv_mma<NFC, true,  false><<<grid, blk, SMEMSZ>>>(hA, (const uint4*)(wp + o1), b1a, nullptr, hB);
    conv_mma<NFC, false, true ><<<grid, blk, SMEMSZ>>>(hB, (const uint4*)(wp + o2), b1b, hA, hA);
    conv_mma<NFC, true,  false><<<grid, blk, SMEMSZ>>>(hA, (const uint4*)(wp + o3), b2a, nullptr, hB);
    conv_mma<NFC, false, true ><<<grid, blk, SMEMSZ>>>(hB, (const uint4*)(wp + o4), b2b, hA, hA);
    conv_mma<NFC, true,  false><<<grid, blk, SMEMSZ>>>(hA, (const uint4*)(wp + o5), b3a, nullptr, hB);
    conv_mma<NFC, false, true ><<<grid, blk, SMEMSZ>>>(hB, (const uint4*)(wp + o6), b3b, hA, hA);

    kpn_fused<<<dim3(WW / 16, HH / 16, BB), 256, FSMEM>>>(
        hA, (const uint4*)(wp + oF), b_out, data, out);
}

// round 17
// speedup vs baseline: 2.0201x; 1.0085x over previous
#include <cuda_runtime.h>
#include <cuda_fp16.h>
#include <cstdint>
#include <cstddef>

#define HH 384
#define WW 384
#define BB 2
#define NFC 64
#define COUTF 35
#define HWSZ (HH * WW)
#define NXSLOT (BB * 4 * HWSZ)
#define NWSLOT 65664   // 4608 + 6*9216 + 5760

__device__ uint2 g_hA[(size_t)BB * 16 * HWSZ];
__device__ uint2 g_hB[(size_t)BB * 16 * HWSZ];
__device__ uint2 g_xin[(size_t)BB * 4 * HWSZ];
__device__ uint2 g_wpack[NWSLOT];

__device__ __forceinline__ uint32_t smem_u32(const void* p) {
    uint32_t a;
    asm("{ .reg .u64 t; cvta.to.shared.u64 t, %1; cvt.u32.u64 %0, t; }" : "=r"(a) : "l"(p));
    return a;
}
__device__ __forceinline__ void cpa8(uint32_t sa, const void* g, int n) {
    asm volatile("cp.async.ca.shared.global [%0], [%1], 8, %2;" :: "r"(sa), "l"(g), "r"(n));
}
__device__ __forceinline__ void cpa16(uint32_t sa, const void* g) {
    asm volatile("cp.async.cg.shared.global [%0], [%1], 16;" :: "r"(sa), "l"(g));
}
#define CPA_COMMIT() asm volatile("cp.async.commit_group;" ::: "memory")
#define CPA_WAIT0()  asm volatile("cp.async.wait_group 0;" ::: "memory")
#define CPA_WAIT1()  asm volatile("cp.async.wait_group 1;" ::: "memory")

__device__ __forceinline__ void mma_f16(float* d, uint32_t a0, uint32_t a1,
                                        uint32_t a2, uint32_t a3,
                                        uint32_t b0, uint32_t b1) {
    asm volatile("mma.sync.aligned.m16n8k16.row.col.f32.f16.f16.f32 "
                 "{%0,%1,%2,%3}, {%4,%5,%6,%7}, {%8,%9}, {%0,%1,%2,%3};"
                 : "+f"(d[0]), "+f"(d[1]), "+f"(d[2]), "+f"(d[3])
                 : "r"(a0), "r"(a1), "r"(a2), "r"(a3), "r"(b0), "r"(b1));
}
__device__ __forceinline__ uint32_t h2bits(float a, float b) {
    __half2 h = __floats2half2_rn(a, b);
    return *(uint32_t*)&h;
}
__device__ __forceinline__ float2 h2f(uint32_t u) {
    return __half22float2(*(__half2*)&u);
}

// ---------------- fused prepass: pack input + ALL weights to fp16 ------------
__global__ void prepass(const float* __restrict__ xsrc, uint2* __restrict__ xdst,
                        const float* __restrict__ w0, const float* __restrict__ w1,
                        const float* __restrict__ w2, const float* __restrict__ w3,
                        const float* __restrict__ w4, const float* __restrict__ w5,
                        const float* __restrict__ w6, const float* __restrict__ w7,
                        uint2* __restrict__ wp)
{
    int idx = blockIdx.x * 256 + threadIdx.x;
    if (idx < NXSLOT) {
        int b = idx / (4 * HWSZ);
        int rem = idx - b * 4 * HWSZ;
        int q = rem / HWSZ;
        int pix = rem - q * HWSZ;
        uint2 u; u.x = 0; u.y = 0;
        if (q == 0)
            u.x = h2bits(xsrc[(size_t)b * 2 * HWSZ + pix],
                         xsrc[(size_t)(b * 2 + 1) * HWSZ + pix]);
        xdst[idx] = u;
        return;
    }
    int wk = idx - NXSLOT;
    if (wk >= NWSLOT) return;

    if (wk < 59904) {
        const float* tbl[7] = {w0, w1, w2, w3, w4, w5, w6};
        int L, c32, slot, CIN;
        if (wk < 4608) { L = 0; c32 = 0; slot = wk; CIN = 2; }
        else {
            int r = wk - 4608;
            L = 1 + r / 9216;
            int r2 = r - (L - 1) * 9216;
            c32 = r2 / 4608;
            slot = r2 - c32 * 4608;
            CIN = NFC;
        }
        const float* wgt = tbl[L];
        int tap = slot >> 9, rr = slot & 511, co = rr >> 3, j = rr & 7;
        int g = c32 * 2 + (j >> 2), q = j & 3;
        int c0 = g * 16 + 2 * q;
        float f0 = 0.f, f1 = 0.f, f2 = 0.f, f3 = 0.f;
        if (c0 < CIN)     f0 = wgt[((size_t)co * CIN + c0) * 9 + tap];
        if (c0 + 1 < CIN) f1 = wgt[((size_t)co * CIN + c0 + 1) * 9 + tap];
        if (c0 + 8 < CIN) f2 = wgt[((size_t)co * CIN + c0 + 8) * 9 + tap];
        if (c0 + 9 < CIN) f3 = wgt[((size_t)co * CIN + c0 + 9) * 9 + tap];
        uint2 u; u.x = h2bits(f0, f1); u.y = h2bits(f2, f3);
        wp[wk] = u;
    } else {
        int rem = wk - 59904;
        int c = rem / 1440;
        int slot = rem - c * 1440;
        int tap = slot / 160;
        int r2 = slot - tap * 160;
        int co = r2 >> 2, q = r2 & 3;
        int c0 = c * 16 + 2 * q;
        float f0 = 0.f, f1 = 0.f, f2 = 0.f, f3 = 0.f;
        if (co < COUTF) {
            f0 = w7[((size_t)co * NFC + c0) * 9 + tap];
            f1 = w7[((size_t)co * NFC + c0 + 1) * 9 + tap];
            f2 = w7[((size_t)co * NFC + c0 + 8) * 9 + tap];
            f3 = w7[((size_t)co * NFC + c0 + 9) * 9 + tap];
        }
        uint2 u; u.x = h2bits(f0, f1); u.y = h2bits(f2, f3);
        wp[wk] = u;
    }
}

// ---------------------------------------------------------------------------
// 3x3 conv as implicit GEMM, fp16 m16n8k16, 32-channel K-chunks, both chunks
// prefetched up-front. K-HALF OUTER loop: per-iteration live regs ~80 ->
// ptxas can software-pipeline tap t+1 fragment loads under tap t MMAs.
// Tile 64 px x 8 rows x 64 co; 512 thr = 16 warps; warp tile mt=4 x nt=4.
// ---------------------------------------------------------------------------
template<int CIN, bool RELU, bool RESID>
__global__ __launch_bounds__(512, 1)
void conv_mma(const uint2* __restrict__ in, const uint4* __restrict__ wsrc,
              const float* __restrict__ bias, const uint2* __restrict__ res,
              uint2* __restrict__ op)
{
    constexpr int CH32 = (CIN + 31) / 32;
    constexpr int NH   = (CIN == 2) ? 1 : 2;   // k-halves per chunk
    constexpr int PLG  = (CIN == 2) ? 4 : 8;
    constexpr int PLB  = (CIN == 2) ? 4 : 16;
    extern __shared__ char smem[];
    const uint32_t sbase = smem_u32(smem);

    const int t = threadIdx.x, lane = t & 31, wid = t >> 5;
    const int wm = wid & 7, wn = wid >> 3;
    const int x0 = blockIdx.x * 64, y0 = blockIdx.y * 8, b = blockIdx.z;
    const int gid = lane >> 2, tid4 = lane & 3;

    int xsoff[11], xgoff[11];
    uint32_t xfl = 0;
    #pragma unroll
    for (int s = 0; s < 11; ++s) {
        xsoff[s] = -1; xgoff[s] = 0;
        int ii = t + 512 * s;
        if (ii < 5440) {
            int pr = ii / 68, sc = ii - pr * 68;
            int p = pr & 7, r = pr >> 3;
            int gy = y0 - 1 + r, gx = x0 + sc - 1;
            if (sc < 66) {
                xsoff[s] = p * 684 + r * 68 + sc;
                if (p < PLG && gy >= 0 && gy < HH && gx >= 0 && gx < WW) {
                    xgoff[s] = p * HWSZ + gy * WW + gx;
                    xfl |= 1u << s;
                }
            }
        }
    }

    float acc[4][4][4];
    #pragma unroll
    for (int mt = 0; mt < 4; ++mt)
        #pragma unroll
        for (int nt = 0; nt < 4; ++nt)
            #pragma unroll
            for (int k = 0; k < 4; ++k) acc[mt][nt][k] = 0.f;

    const int abase = tid4 * 684 + wm * 68 + gid;
    const uint2* inb_p = in + (size_t)b * PLB * HWSZ;

    auto prefetch = [&](int c) {
        const uint32_t xb = sbase + c * 43776;
        const uint2* inc = inb_p + (size_t)c * 8 * HWSZ;
        #pragma unroll
        for (int s = 0; s < 11; ++s) {
            int so = xsoff[s];
            if (so >= 0) {
                int n = (xfl >> s) & 1 ? 8 : 0;
                cpa8(xb + so * 8, inc + xgoff[s], n);
            }
        }
        const uint32_t wbse = sbase + 87552 + c * 55296;
        const uint4* ws = wsrc + (size_t)c * 2304;
        #pragma unroll
        for (int s5 = 0; s5 < 5; ++s5) {
            int i = t + 512 * s5;
            if (i < 2304) {
                int tap = i >> 8, r = i & 255, co = r >> 2, qp = r & 3;
                cpa16(wbse + (tap * 768 + co * 12 + qp * 2) * 8, ws + i);
            }
        }
        CPA_COMMIT();
    };

    auto compute = [&](int c) {
        const uint2* sX = (const uint2*)(smem + c * 43776);
        const uint2* sW = (const uint2*)(smem + 87552 + c * 55296);
        #pragma unroll
        for (int h = 0; h < NH; ++h) {
            const uint2* sXh = sX + h * 2736;
            const uint2* sWh = sW + h * 4;
            #pragma unroll
            for (int tap = 0; tap < 9; ++tap) {
                const int dy = tap / 3, dx = tap - dy * 3;
                uint2 bf[4];
                #pragma unroll
                for (int nt = 0; nt < 4; ++nt)
                    bf[nt] = sWh[tap * 768 + (wn * 32 + nt * 8 + gid) * 12 + tid4];
                #pragma unroll
                for (int mt = 0; mt < 4; ++mt) {
                    int ab = abase + dy * 68 + dx + mt * 16;
                    uint2 u = sXh[ab], v = sXh[ab + 8];
                    #pragma unroll
                    for (int nt = 0; nt < 4; ++nt)
                        mma_f16(acc[mt][nt], u.x, v.x, u.y, v.y, bf[nt].x, bf[nt].y);
                }
            }
        }
    };

    if (CH32 == 2) {
        prefetch(0);
        prefetch(1);
        CPA_WAIT1();
        __syncthreads();
        compute(0);
        CPA_WAIT0();
        __syncthreads();
        compute(1);
    } else {
        prefetch(0);
        CPA_WAIT0();
        __syncthreads();
        compute(0);
    }

    const int y = y0 + wm;
    #pragma unroll
    for (int cq = 0; cq < 2; ++cq) {
        int cb = wn * 32 + 16 * cq + 2 * tid4;
        float bx0 = bias[cb], bx1 = bias[cb + 1];
        float by0 = bias[cb + 8], by1 = bias[cb + 9];
        size_t plane = (((size_t)b * 4 + wn * 2 + cq) * 4 + tid4) * HWSZ + (size_t)y * WW;
        #pragma unroll
        for (int mt = 0; mt < 4; ++mt) {
            #pragma unroll
            for (int h8 = 0; h8 < 2; ++h8) {
                int x = x0 + mt * 16 + gid + h8 * 8;
                float vx0 = acc[mt][2 * cq][h8 * 2 + 0] + bx0;
                float vx1 = acc[mt][2 * cq][h8 * 2 + 1] + bx1;
                float vy0 = acc[mt][2 * cq + 1][h8 * 2 + 0] + by0;
                float vy1 = acc[mt][2 * cq + 1][h8 * 2 + 1] + by1;
                if (RELU) {
                    vx0 = fmaxf(vx0, 0.f); vx1 = fmaxf(vx1, 0.f);
                    vy0 = fmaxf(vy0, 0.f); vy1 = fmaxf(vy1, 0.f);
                }
                size_t oi = plane + x;
                if (RESID) {
                    uint2 r = res[oi];
                    float2 lo = h2f(r.x), hi = h2f(r.y);
                    vx0 += lo.x; vx1 += lo.y; vy0 += hi.x; vy1 += hi.y;
                }
                uint2 o; o.x = h2bits(vx0, vx1); o.y = h2bits(vy0, vy1);
                op[oi] = o;
            }
        }
    }
}

// ---------------- KPN tables ----------------
#define FST 33
#define FTH 30

struct TEnt { int lo, hi, doff; bool inR; float a, b; };

__host__ __device__ constexpr double csqrt_(double x) {
    double g = x > 1.0 ? x : 1.0;
    for (int i = 0; i < 100; ++i) g = 0.5 * (g + x / g);
    return g;
}
__host__ __device__ constexpr TEnt tentry(int w, int p) {
    const int K = 2 * w - 1, r = w - 1, coff = w * (w - 1) / 2 - 1;
    const int i = p / K, j = p % K;
    TEnt e{};
    e.doff = (i - r) * FST + (j - r);
    const int s2 = (i - r) * (i - r) + (j - r) * (j - r);
    int q = 0;
    while ((q + 1) * (q + 1) <= s2) ++q;
    if (q * q == s2) {
        if (q > r) { e.inR = false; e.lo = coff; e.hi = coff; e.a = 0.f; e.b = 0.f; }
        else       { e.inR = true;  e.lo = coff + q; e.hi = coff + q; e.a = 1.f; e.b = 0.f; }
    } else {
        if (q >= r) { e.inR = false; e.lo = coff; e.hi = coff; e.a = 0.f; e.b = 0.f; }
        else {
            double d = csqrt_((double)s2);
            e.inR = true; e.lo = coff + q; e.hi = coff + q + 1;
            e.a = (float)((double)(q + 1) - d);
            e.b = (float)(d - (double)q);
        }
    }
    return e;
}

template<int W, int Lo, int N>
struct KLoop {
    static __device__ __forceinline__ void run(const float (&c)[COUTF], const float* __restrict__ sF,
                                               int ctr, float& den, float& num) {
        KLoop<W, Lo, N / 2>::run(c, sF, ctr, den, num);
        KLoop<W, Lo + N / 2, N - N / 2>::run(c, sF, ctr, den, num);
    }
};
template<int W, int Lo>
struct KLoop<W, Lo, 1> {
    static __device__ __forceinline__ void run(const float (&c)[COUTF], const float* __restrict__ sF,
                                               int ctr, float& den, float& num) {
        constexpr TEnt e = tentry(W, Lo);
        float patch = sF[ctr + e.doff];
        if constexpr (e.inR) {
            float v = e.a * c[e.lo] + e.b * c[e.hi];
            float tt = __expf(v);
            den += tt; num += tt * patch;
        } else { den += 1.f; num += patch; }
    }
};
template<int W, int Lo>
struct KLoop<W, Lo, 0> {
    static __device__ __forceinline__ void run(const float (&)[COUTF], const float* __restrict__,
                                               int, float&, float&) {}
};

template<int W>
__device__ __forceinline__ float section_run(const float (&c)[COUTF], const float* __restrict__ sF, int ctr) {
    constexpr int K = 2 * W - 1;
    float den = 0.f, num = 0.f;
    KLoop<W, 0, K * K>::run(c, sF, ctr, den, num);
    return num / den;
}

// ---------------------------------------------------------------------------
// FUSED out-conv (64 -> 35, padded to 40) + KPN aggregation.
// ---------------------------------------------------------------------------
__global__ __launch_bounds__(256)
void kpn_fused(const uint2* __restrict__ hA, const uint4* __restrict__ wsrc,
               const float* __restrict__ bias, const float* __restrict__ data,
               float* __restrict__ out)
{
    extern __shared__ char smem[];
    const uint32_t sbase = smem_u32(smem);
    float* sCore = (float*)(smem + 44288);
    float* sF    = (float*)(smem + 82176);

    const int t = threadIdx.x, lane = t & 31, wid = t >> 5;
    const int gid = lane >> 2, tid4 = lane & 3;
    const int x0 = blockIdx.x * 16, y0 = blockIdx.y * 16, b = blockIdx.z;

    {
        const int oy = y0 - 7, ox = x0 - 7;
        for (int idx = t; idx < FTH * FTH; idx += 256) {
            int fy = idx / FTH, fx = idx - fy * FTH;
            int gy = oy + fy, gx = ox + fx;
            float v = 0.f;
            if (gy >= 0 && gy < HH && gx >= 0 && gx < WW)
                v = data[((size_t)b * HH + gy) * WW + gx];
            sF[fy * FST + fx] = v;
        }
    }

    int xsoff[6], xgoff[6];
    uint32_t xfl = 0;
    #pragma unroll
    for (int s6 = 0; s6 < 6; ++s6) {
        xsoff[s6] = -1; xgoff[s6] = 0;
        int ii = t + 256 * s6;
        if (ii < 1296) {
            int q = ii / 324, rm = ii - q * 324, r = rm / 18, s = rm - r * 18;
            int gy = y0 - 1 + r, gx = x0 - 1 + s;
            xsoff[s6] = q * 332 + r * 18 + s;
            if (gy >= 0 && gy < HH && gx >= 0 && gx < WW) {
                xgoff[s6] = q * HWSZ + gy * WW + gx;
                xfl |= 1u << s6;
            }
        }
    }

    const uint2* inb_p = hA + (size_t)b * 16 * HWSZ;
    auto prefetch = [&](int c) {
        const uint32_t xb = sbase + (c & 1) * 10624;
        const uint2* inc = inb_p + (size_t)c * 4 * HWSZ;
        #pragma unroll
        for (int s6 = 0; s6 < 6; ++s6) {
            int so = xsoff[s6];
            if (so >= 0) {
                int n = (xfl >> s6) & 1 ? 8 : 0;
                cpa8(xb + so * 8, inc + xgoff[s6], n);
            }
        }
        const uint32_t wbse = sbase + 21248 + (c & 1) * 11520;
        const uint4* ws = wsrc + (size_t)c * 720;
        #pragma unroll
        for (int s3 = 0; s3 < 3; ++s3) {
            int i = t + 256 * s3;
            if (i < 720) cpa16(wbse + i * 16, ws + i);
        }
        CPA_COMMIT();
    };

    float acc[2][5][4];
    #pragma unroll
    for (int mt = 0; mt < 2; ++mt)
        #pragma unroll
        for (int nt = 0; nt < 5; ++nt)
            #pragma unroll
            for (int k = 0; k < 4; ++k) acc[mt][nt][k] = 0.f;

    const int bbase = gid * 4 + tid4;

    prefetch(0);
    for (int c = 0; c < 4; ++c) {
        CPA_WAIT0();
        __syncthreads();
        if (c + 1 < 4) prefetch(c + 1);
        const uint2* sX2 = (const uint2*)(smem + (c & 1) * 10624);
        const uint2* sW2 = (const uint2*)(smem + 21248 + (c & 1) * 11520);

        #pragma unroll
        for (int tap = 0; tap < 9; ++tap) {
            const int dy = tap / 3, dx = tap - dy * 3;
            uint2 bf[5];
            #pragma unroll
            for (int nt = 0; nt < 5; ++nt)
                bf[nt] = sW2[tap * 160 + nt * 32 + bbase];
            #pragma unroll
            for (int mt = 0; mt < 2; ++mt) {
                int yw = 2 * wid + mt;
                uint2 u = sX2[tid4 * 332 + (yw + dy) * 18 + gid + dx];
                uint2 v = sX2[tid4 * 332 + (yw + dy) * 18 + gid + dx + 8];
                #pragma unroll
                for (int nt = 0; nt < 5; ++nt)
                    mma_f16(acc[mt][nt], u.x, v.x, u.y, v.y, bf[nt].x, bf[nt].y);
            }
        }
    }

    #pragma unroll
    for (int nt = 0; nt < 5; ++nt) {
        int co0 = nt * 8 + 2 * tid4, co1 = co0 + 1;
        float bv0 = (co0 < COUTF) ? bias[co0] : 0.f;
        float bv1 = (co1 < COUTF) ? bias[co1] : 0.f;
        #pragma unroll
        for (int mt = 0; mt < 2; ++mt) {
            int yw = 2 * wid + mt;
            int px0 = yw * 16 + gid, px1 = px0 + 8;
            if (co0 < COUTF) {
                sCore[px0 * 37 + co0] = acc[mt][nt][0] + bv0;
                sCore[px1 * 37 + co0] = acc[mt][nt][2] + bv0;
            }
            if (co1 < COUTF) {
                sCore[px0 * 37 + co1] = acc[mt][nt][1] + bv1;
                sCore[px1 * 37 + co1] = acc[mt][nt][3] + bv1;
            }
        }
    }
    __syncthreads();

    const int tx = t & 15, ty = t >> 4;
    const int px = ty * 16 + tx;
    float c[COUTF];
    #pragma unroll
    for (int ch = 0; ch < COUTF; ++ch)
        c[ch] = fabsf(sCore[px * 37 + ch]);

    const int ctr = (ty + 7) * FST + (tx + 7);
    float pred = 0.f;
    pred += section_run<2>(c, sF, ctr);
    pred += section_run<3>(c, sF, ctr);
    pred += section_run<4>(c, sF, ctr);
    pred += section_run<5>(c, sF, ctr);
    pred += section_run<6>(c, sF, ctr);
    pred += section_run<7>(c, sF, ctr);
    pred += section_run<8>(c, sF, ctr);

    out[((size_t)b * HH + y0 + ty) * WW + x0 + tx] = pred;
}

// ------------------------------- launch --------------------------------------
#define SMEMSZ 198144
#define FSMEM  86136

extern "C" void kernel_launch(void* const* d_in, const int* in_sizes, int n_in,
                              void* d_out, int out_size) {
    (void)in_sizes; (void)n_in; (void)out_size;
    const float* data_with_est = (const float*)d_in[0];
    const float* data  = (const float*)d_in[1];
    const float* w_first = (const float*)d_in[2];
    const float* b_first = (const float*)d_in[3];
    const float* w1a = (const float*)d_in[4];
    const float* b1a = (const float*)d_in[5];
    const float* w1b = (const float*)d_in[6];
    const float* b1b = (const float*)d_in[7];
    const float* w2a = (const float*)d_in[8];
    const float* b2a = (const float*)d_in[9];
    const float* w2b = (const float*)d_in[10];
    const float* b2b = (const float*)d_in[11];
    const float* w3a = (const float*)d_in[12];
    const float* b3a = (const float*)d_in[13];
    const float* w3b = (const float*)d_in[14];
    const float* b3b = (const float*)d_in[15];
    const float* w_out = (const float*)d_in[16];
    const float* b_out = (const float*)d_in[17];
    float* out = (float*)d_out;

    uint2 *hA = nullptr, *hB = nullptr, *xin = nullptr, *wp = nullptr;
    cudaGetSymbolAddress((void**)&hA, g_hA);
    cudaGetSymbolAddress((void**)&hB, g_hB);
    cudaGetSymbolAddress((void**)&xin, g_xin);
    cudaGetSymbolAddress((void**)&wp, g_wpack);

    const size_t o0 = 0, o1 = 4608, o2 = 13824, o3 = 23040,
                 o4 = 32256, o5 = 41472, o6 = 50688, oF = 59904;

    cudaFuncSetAttribute(conv_mma<2, false, false>, cudaFuncAttributeMaxDynamicSharedMemorySize, SMEMSZ);
    cudaFuncSetAttribute(conv_mma<NFC, true, false>, cudaFuncAttributeMaxDynamicSharedMemorySize, SMEMSZ);
    cudaFuncSetAttribute(conv_mma<NFC, false, true>, cudaFuncAttributeMaxDynamicSharedMemorySize, SMEMSZ);
    cudaFuncSetAttribute(kpn_fused, cudaFuncAttributeMaxDynamicSharedMemorySize, FSMEM);

    prepass<<<(NXSLOT + NWSLOT + 255) / 256, 256>>>(
        data_with_est, xin, w_first, w1a, w1b, w2a, w2b, w3a, w3b, w_out, wp);

    dim3 grid(WW / 64, HH / 8, BB), blk(512);

    conv_mma<2, false, false><<<grid, blk, SMEMSZ>>>(xin, (const uint4*)(wp + o0), b_first, nullptr, hA);
    conv_mma<NFC, true,  false><<<grid, blk, SMEMSZ>>>(hA, (const uint4*)(wp + o1), b1a, nullptr, hB);
    conv_mma<NFC, false, true ><<<grid, blk, SMEMSZ>>>(hB, (const uint4*)(wp + o2), b1b, hA, hA);
    conv_mma<NFC, true,  false><<<grid, blk, SMEMSZ>>>(hA, (const uint4*)(wp + o3), b2a, nullptr, hB);
    conv_mma<NFC, false, true ><<<grid, blk, SMEMSZ>>>(hB, (const uint4*)(wp + o4), b2b, hA, hA);
    conv_mma<NFC, true,  false><<<grid, blk, SMEMSZ>>>(hA, (const uint4*)(wp + o5), b3a, nullptr, hB);
    conv_mma<NFC, false, true ><<<grid, blk, SMEMSZ>>>(hB, (const uint4*)(wp + o6), b3b, hA, hA);

    kpn_fused<<<dim3(WW / 16, HH / 16, BB), 256, FSMEM>>>(
        hA, (const uint4*)(wp + oF), b_out, data, out);
}